// round 9
// baseline (speedup 1.0000x reference)
#include <cuda_runtime.h>
#include <cuda_fp16.h>
#include <cstdint>

#define B_    2
#define T_    2048
#define D_    4096
#define H_    32
#define KVH_  8
#define DH_   128
#define QS_   (H_*DH_)
#define KS_   (KVH_*DH_)
#define QKVN_ (QS_ + 2*KS_)
#define M_    (B_*T_)

// Scratch
__device__ float  g_qkv[(size_t)M_ * QKVN_];
__device__ float  g_y[(size_t)M_ * QS_];
// int8 digit planes + row scales
__device__ int8_t g_xd1[(size_t)M_ * D_];
__device__ int8_t g_xd0[(size_t)M_ * D_];
__device__ int8_t g_wd1[(size_t)QKVN_ * D_];
__device__ int8_t g_wd0[(size_t)QKVN_ * D_];
__device__ int8_t g_od1[(size_t)D_ * QS_];
__device__ int8_t g_od0[(size_t)D_ * QS_];
__device__ int8_t g_yd1[(size_t)M_ * QS_];
__device__ int8_t g_yd0[(size_t)M_ * QS_];
__device__ float  g_sx[M_];
__device__ float  g_sw[QKVN_];
__device__ float  g_so[D_];
__device__ float  g_sy[M_];
// attention fp16 planes
__device__ __half g_Qh[(size_t)M_ * QS_];
__device__ __half g_Ql[(size_t)M_ * QS_];
__device__ __half g_Kh[(size_t)M_ * KS_];
__device__ __half g_Kl[(size_t)M_ * KS_];
__device__ __half g_Vh[(size_t)M_ * KS_];
__device__ __half g_Vl[(size_t)M_ * KS_];

// ---------------------------------------------------------------------------
__device__ __forceinline__ uint32_t smem_u32(const void* p) {
    uint32_t a;
    asm("{ .reg .u64 t; cvta.to.shared.u64 t, %1; cvt.u32.u64 %0, t; }"
        : "=r"(a) : "l"(p));
    return a;
}
__device__ __forceinline__ void cpasync16(uint32_t s, const void* g) {
    asm volatile("cp.async.cg.shared.global [%0], [%1], 16;" :: "r"(s), "l"(g));
}
#define CP_COMMIT() asm volatile("cp.async.commit_group;" ::: "memory")
#define CP_WAIT(N)  asm volatile("cp.async.wait_group %0;" :: "n"(N) : "memory")

#define LDSM_X4(r, addr)                                                      \
    asm volatile("ldmatrix.sync.aligned.m8n8.x4.shared.b16 {%0,%1,%2,%3}, [%4];" \
        : "=r"((r)[0]), "=r"((r)[1]), "=r"((r)[2]), "=r"((r)[3]) : "r"(addr))
#define LDSM_X4_T(r, addr)                                                    \
    asm volatile("ldmatrix.sync.aligned.m8n8.x4.trans.shared.b16 {%0,%1,%2,%3}, [%4];" \
        : "=r"((r)[0]), "=r"((r)[1]), "=r"((r)[2]), "=r"((r)[3]) : "r"(addr))

#define MMAH(d, a, b0, b1)                                                    \
    asm volatile("mma.sync.aligned.m16n8k16.row.col.f32.f16.f16.f32 "         \
        "{%0,%1,%2,%3}, {%4,%5,%6,%7}, {%8,%9}, {%0,%1,%2,%3};"               \
        : "+f"((d)[0]), "+f"((d)[1]), "+f"((d)[2]), "+f"((d)[3])              \
        : "r"((a)[0]), "r"((a)[1]), "r"((a)[2]), "r"((a)[3]), "r"(b0), "r"(b1))

#define MMAI(d, a, b0, b1)                                                    \
    asm volatile("mma.sync.aligned.m16n8k32.row.col.s32.s8.s8.s32 "           \
        "{%0,%1,%2,%3}, {%4,%5,%6,%7}, {%8,%9}, {%0,%1,%2,%3};"               \
        : "+r"((d)[0]), "+r"((d)[1]), "+r"((d)[2]), "+r"((d)[3])              \
        : "r"((a)[0]), "r"((a)[1]), "r"((a)[2]), "r"((a)[3]), "r"(b0), "r"(b1))

__device__ __forceinline__ uint32_t packh2(float a, float b) {
    __half2 h = __floats2half2_rn(a, b);
    return *reinterpret_cast<uint32_t*>(&h);
}

// ---------------------------------------------------------------------------
// Row quantize: x = q*(128*d1 + d0), q = rowmax/16256, K = 4096 fixed.
// One 256-thread block per row.
// ---------------------------------------------------------------------------
__global__ void quant_kernel(const float* __restrict__ in,
                             int8_t* __restrict__ d1p, int8_t* __restrict__ d0p,
                             float* __restrict__ scale)
{
    const int row = blockIdx.x, tid = threadIdx.x;
    const float4* src = (const float4*)(in + (size_t)row * 4096);
    float mx = 0.0f;
#pragma unroll
    for (int i = 0; i < 4; i++) {
        float4 v = src[tid + i * 256];
        mx = fmaxf(mx, fmaxf(fmaxf(fabsf(v.x), fabsf(v.y)),
                             fmaxf(fabsf(v.z), fabsf(v.w))));
    }
#pragma unroll
    for (int o = 16; o > 0; o >>= 1)
        mx = fmaxf(mx, __shfl_xor_sync(0xffffffffu, mx, o));
    __shared__ float smx[8];
    __shared__ float sq;
    if ((tid & 31) == 0) smx[tid >> 5] = mx;
    __syncthreads();
    if (tid == 0) {
        float m = smx[0];
#pragma unroll
        for (int i = 1; i < 8; i++) m = fmaxf(m, smx[i]);
        float q = fmaxf(m, 1e-20f) * (1.0f / 16256.0f);
        sq = q;
        scale[row] = q;
    }
    __syncthreads();
    const float rq = 1.0f / sq;
    char4* o1 = (char4*)(d1p + (size_t)row * 4096);
    char4* o0 = (char4*)(d0p + (size_t)row * 4096);
#pragma unroll
    for (int i = 0; i < 4; i++) {
        float4 v = src[tid + i * 256];
        float w0 = v.x * rq, w1 = v.y * rq, w2 = v.z * rq, w3 = v.w * rq;
        float h0 = rintf(w0 * 0.0078125f), h1 = rintf(w1 * 0.0078125f);
        float h2 = rintf(w2 * 0.0078125f), h3 = rintf(w3 * 0.0078125f);
        char4 c1 = make_char4((char)(int)h0, (char)(int)h1, (char)(int)h2, (char)(int)h3);
        char4 c0 = make_char4((char)(int)rintf(w0 - 128.0f * h0),
                              (char)(int)rintf(w1 - 128.0f * h1),
                              (char)(int)rintf(w2 - 128.0f * h2),
                              (char)(int)rintf(w3 - 128.0f * h3));
        o1[tid + i * 256] = c1;
        o0[tid + i * 256] = c0;
    }
}

// ---------------------------------------------------------------------------
// 3-digit int8 IMMA GEMM: C[M][N] = qa*qb*(16384*S11 + 128*(S10+S01))
// CTA 128(M)x64(N), BK=64 bytes, 256 thr (8 warps: 4x2, warp 32x32), 2 CTA/SM.
// ---------------------------------------------------------------------------
#define IST_   80
#define APL8   (128 * IST_)            // 10240
#define BPL8   (64 * IST_)             // 5120
#define ISTG   (2 * APL8 + 2 * BPL8)   // 30720
#define IGSMEM (2 * ISTG)              // 61440

__global__ __launch_bounds__(256, 2) void gemm3i8_kernel(
    const int8_t* __restrict__ A1, const int8_t* __restrict__ A0,
    const int8_t* __restrict__ B1, const int8_t* __restrict__ B0,
    const float* __restrict__ qa, const float* __restrict__ qb,
    float* __restrict__ C, int M, int N, int K)
{
    extern __shared__ char smem[];
    const uint32_t sbase = smem_u32(smem);
    const int tid  = threadIdx.x;
    const int lane = tid & 31;
    const int wid  = tid >> 5;
    const int wm   = wid >> 1;       // 0..3
    const int wn   = wid & 1;        // 0..1

    const int bm = blockIdx.y * 128;
    const int bn = blockIdx.x * 64;
    const int nk = K >> 6;

    const int8_t* gA1 = A1 + (size_t)bm * K;
    const int8_t* gA0 = A0 + (size_t)bm * K;
    const int8_t* gB1 = B1 + (size_t)bn * K;
    const int8_t* gB0 = B0 + (size_t)bn * K;

    const int rowAc = tid >> 2, segA = tid & 3;            // A loader: 2 chunks
    const int rowAc2 = (tid + 256) >> 2;
    const int rowBc = tid >> 2, segB = tid & 3;            // B loader: 1 chunk

    int acc1[2][4][4], acc2[2][4][4];
#pragma unroll
    for (int mt = 0; mt < 2; mt++)
#pragma unroll
        for (int nt = 0; nt < 4; nt++)
#pragma unroll
            for (int q = 0; q < 4; q++) { acc1[mt][nt][q] = 0; acc2[mt][nt][q] = 0; }

    // prologue: chunk 0 -> stage 0
    {
        cpasync16(sbase + rowAc * IST_ + segA * 16, gA1 + (size_t)rowAc * K + segA * 16);
        cpasync16(sbase + rowAc2 * IST_ + segA * 16, gA1 + (size_t)rowAc2 * K + segA * 16);
        cpasync16(sbase + APL8 + rowAc * IST_ + segA * 16, gA0 + (size_t)rowAc * K + segA * 16);
        cpasync16(sbase + APL8 + rowAc2 * IST_ + segA * 16, gA0 + (size_t)rowAc2 * K + segA * 16);
        cpasync16(sbase + 2 * APL8 + rowBc * IST_ + segB * 16, gB1 + (size_t)rowBc * K + segB * 16);
        cpasync16(sbase + 2 * APL8 + BPL8 + rowBc * IST_ + segB * 16, gB0 + (size_t)rowBc * K + segB * 16);
        CP_COMMIT();
    }

    const int rowA = lane & 15;
    const int colA = (lane >> 4) * 16;
    const int rowB = (lane & 7) + ((lane & 16) ? 8 : 0);
    const int colB = ((lane >> 3) & 1) * 16;

    for (int c = 0; c < nk; c++) {
        const int cur = c & 1;
        if (c + 1 < nk) {
            const int k0 = (c + 1) << 6;
            const uint32_t st = sbase + (cur ^ 1) * ISTG;
            cpasync16(st + rowAc * IST_ + segA * 16, gA1 + (size_t)rowAc * K + k0 + segA * 16);
            cpasync16(st + rowAc2 * IST_ + segA * 16, gA1 + (size_t)rowAc2 * K + k0 + segA * 16);
            cpasync16(st + APL8 + rowAc * IST_ + segA * 16, gA0 + (size_t)rowAc * K + k0 + segA * 16);
            cpasync16(st + APL8 + rowAc2 * IST_ + segA * 16, gA0 + (size_t)rowAc2 * K + k0 + segA * 16);
            cpasync16(st + 2 * APL8 + rowBc * IST_ + segB * 16, gB1 + (size_t)rowBc * K + k0 + segB * 16);
            cpasync16(st + 2 * APL8 + BPL8 + rowBc * IST_ + segB * 16, gB0 + (size_t)rowBc * K + k0 + segB * 16);
            CP_COMMIT();
            CP_WAIT(1);
        } else {
            CP_WAIT(0);
        }
        __syncthreads();

        const uint32_t st  = sbase + cur * ISTG;
        const uint32_t sA1 = st;
        const uint32_t sA0 = st + APL8;
        const uint32_t sB1 = st + 2 * APL8;
        const uint32_t sB0 = st + 2 * APL8 + BPL8;

#pragma unroll
        for (int ks = 0; ks < 2; ks++) {
            const int kb = ks * 32;
            uint32_t a1f[2][4], a0f[2][4];
#pragma unroll
            for (int mt = 0; mt < 2; mt++) {
                uint32_t off = (uint32_t)((wm * 32 + mt * 16 + rowA) * IST_ + colA + kb);
                LDSM_X4(a1f[mt], sA1 + off);
                LDSM_X4(a0f[mt], sA0 + off);
            }
#pragma unroll
            for (int nb = 0; nb < 2; nb++) {
                uint32_t b1f[4], b0f[4];
                uint32_t off = (uint32_t)((wn * 32 + nb * 16 + rowB) * IST_ + colB + kb);
                LDSM_X4(b1f, sB1 + off);
                LDSM_X4(b0f, sB0 + off);
#pragma unroll
                for (int hf = 0; hf < 2; hf++)
#pragma unroll
                    for (int mt = 0; mt < 2; mt++) {
                        const int nt = 2 * nb + hf;
                        MMAI(acc1[mt][nt], a1f[mt], b1f[2 * hf], b1f[2 * hf + 1]);
                        MMAI(acc2[mt][nt], a1f[mt], b0f[2 * hf], b0f[2 * hf + 1]);
                        MMAI(acc2[mt][nt], a0f[mt], b1f[2 * hf], b1f[2 * hf + 1]);
                    }
            }
        }
        __syncthreads();
    }

    // epilogue: combine digits and scale
#pragma unroll
    for (int mt = 0; mt < 2; mt++) {
        const int r0 = bm + wm * 32 + mt * 16 + (lane >> 2);
        const float qa0 = qa[r0], qa8 = qa[r0 + 8];
#pragma unroll
        for (int nt = 0; nt < 4; nt++) {
            const int col = bn + wn * 32 + nt * 8 + (lane & 3) * 2;
            float2 qbv = *(const float2*)&qb[col];
            float v0 = (16384.0f * (float)acc1[mt][nt][0] + 128.0f * (float)acc2[mt][nt][0]) * qa0 * qbv.x;
            float v1 = (16384.0f * (float)acc1[mt][nt][1] + 128.0f * (float)acc2[mt][nt][1]) * qa0 * qbv.y;
            float v2 = (16384.0f * (float)acc1[mt][nt][2] + 128.0f * (float)acc2[mt][nt][2]) * qa8 * qbv.x;
            float v3 = (16384.0f * (float)acc1[mt][nt][3] + 128.0f * (float)acc2[mt][nt][3]) * qa8 * qbv.y;
            *(float2*)&C[(size_t)r0 * N + col] = make_float2(v0, v1);
            *(float2*)&C[(size_t)(r0 + 8) * N + col] = make_float2(v2, v3);
        }
    }
}

// ---------------------------------------------------------------------------
// Prep: RoPE + split g_qkv into head-major fp16 planes
// ---------------------------------------------------------------------------
__global__ void prep_kernel(const float* __restrict__ pcos,
                            const float* __restrict__ psin)
{
    int idx = blockIdx.x * blockDim.x + threadIdx.x;
    const int total = M_ * 48 * 32;
    if (idx >= total) return;
    int q4 = idx & 31;
    int h  = (idx >> 5) % 48;
    int bt = idx / (32 * 48);
    int t  = bt & (T_ - 1);
    int b  = bt >> 11;

    float4 v = *(const float4*)&g_qkv[(size_t)bt * QKVN_ + h * DH_ + q4 * 4];
    if (h < 40) {
        float2 c = *(const float2*)&pcos[t * 64 + q4 * 2];
        float2 s = *(const float2*)&psin[t * 64 + q4 * 2];
        v = make_float4(v.x * c.x - v.y * s.x, v.x * s.x + v.y * c.x,
                        v.z * c.y - v.w * s.y, v.z * s.y + v.w * c.y);
    }
    __half *ph, *pl;
    size_t off;
    if (h < 32) {
        off = (((size_t)b * H_ + h) * T_ + t) * DH_ + q4 * 4;
        ph = g_Qh; pl = g_Ql;
    } else if (h < 40) {
        off = (((size_t)b * KVH_ + (h - 32)) * T_ + t) * DH_ + q4 * 4;
        ph = g_Kh; pl = g_Kl;
    } else {
        off = (((size_t)b * KVH_ + (h - 40)) * T_ + t) * DH_ + q4 * 4;
        ph = g_Vh; pl = g_Vl;
    }
    __half h0 = __float2half_rn(v.x), h1 = __float2half_rn(v.y);
    __half h2 = __float2half_rn(v.z), h3 = __float2half_rn(v.w);
    ((__half2*)(ph + off))[0] = __halves2half2(h0, h1);
    ((__half2*)(ph + off))[1] = __halves2half2(h2, h3);
    ((__half2*)(pl + off))[0] = __floats2half2_rn(v.x - __half2float(h0), v.y - __half2float(h1));
    ((__half2*)(pl + off))[1] = __floats2half2_rn(v.z - __half2float(h2), v.w - __half2float(h3));
}

// ---------------------------------------------------------------------------
// mma.sync flash attention (causal, GQA), writes fp32 y.
// ---------------------------------------------------------------------------
#define AST_B 272
#define APL_  (64 * AST_B)
#define ASMEM (4 * APL_)

__global__ __launch_bounds__(128, 2) void attn_mma_kernel()
{
    extern __shared__ char sm[];
    const uint32_t sKh = smem_u32(sm);
    const uint32_t sKl = sKh + APL_;
    const uint32_t sVh = sKh + 2 * APL_;
    const uint32_t sVl = sKh + 3 * APL_;

    const int tid = threadIdx.x, lane = tid & 31, w = tid >> 5;
    const int qb = blockIdx.x * 64;
    const int h  = blockIdx.y;
    const int b  = blockIdx.z;
    const int kh = h >> 2;

    const __half* gQh = g_Qh + ((size_t)b * H_ + h) * T_ * DH_;
    const __half* gQl = g_Ql + ((size_t)b * H_ + h) * T_ * DH_;
    const __half* gKh = g_Kh + ((size_t)b * KVH_ + kh) * T_ * DH_;
    const __half* gKl = g_Kl + ((size_t)b * KVH_ + kh) * T_ * DH_;
    const __half* gVh = g_Vh + ((size_t)b * KVH_ + kh) * T_ * DH_;
    const __half* gVl = g_Vl + ((size_t)b * KVH_ + kh) * T_ * DH_;

#pragma unroll
    for (int k = 0; k < 8; k++) {
        int id = tid + 128 * k, r = id >> 4, sg = id & 15;
        cpasync16(sKh + r * AST_B + sg * 16,
                  (const char*)(gQh + (size_t)(qb + r) * DH_) + sg * 16);
        cpasync16(sKl + r * AST_B + sg * 16,
                  (const char*)(gQl + (size_t)(qb + r) * DH_) + sg * 16);
    }
    CP_COMMIT(); CP_WAIT(0);
    __syncthreads();

    uint32_t qh_[8][4], ql_[8][4];
    {
        uint32_t base = (uint32_t)((w * 16 + (lane & 15)) * AST_B + (lane >> 4) * 16);
#pragma unroll
        for (int ks = 0; ks < 8; ks++) {
            LDSM_X4(qh_[ks], sKh + base + ks * 32);
            LDSM_X4(ql_[ks], sKl + base + ks * 32);
        }
    }
    __syncthreads();

    float o[16][4];
#pragma unroll
    for (int nt = 0; nt < 16; nt++)
#pragma unroll
        for (int q = 0; q < 4; q++) o[nt][q] = 0.0f;
    float m0 = -1e30f, m1 = -1e30f, l0 = 0.0f, l1 = 0.0f;

    const int last = qb >> 6;
    const int rowB = (lane & 7) + ((lane & 16) ? 8 : 0);
    const int colB = ((lane >> 3) & 1) * 16;
    const int qrow0 = qb + w * 16 + (lane >> 2);
    const int qrow1 = qrow0 + 8;
    const float sc = 0.08838834764831845f;

    for (int kb = 0; kb <= last; kb++) {
#pragma unroll
        for (int k = 0; k < 8; k++) {
            int id = tid + 128 * k, r = id >> 4, sg = id & 15;
            size_t grow = (size_t)(kb * 64 + r) * DH_;
            uint32_t soff = (uint32_t)(r * AST_B + sg * 16);
            cpasync16(sKh + soff, (const char*)(gKh + grow) + sg * 16);
            cpasync16(sKl + soff, (const char*)(gKl + grow) + sg * 16);
            cpasync16(sVh + soff, (const char*)(gVh + grow) + sg * 16);
            cpasync16(sVl + soff, (const char*)(gVl + grow) + sg * 16);
        }
        CP_COMMIT(); CP_WAIT(0);
        __syncthreads();

        float s[8][4];
#pragma unroll
        for (int nt = 0; nt < 8; nt++)
#pragma unroll
            for (int q = 0; q < 4; q++) s[nt][q] = 0.0f;

#pragma unroll
        for (int ks = 0; ks < 8; ks++) {
            uint32_t kfh[4][4], kfl[4][4];
#pragma unroll
            for (int pr = 0; pr < 4; pr++) {
                uint32_t off = (uint32_t)((pr * 16 + rowB) * AST_B + colB + ks * 32);
                LDSM_X4(kfh[pr], sKh + off);
                LDSM_X4(kfl[pr], sKl + off);
            }
#pragma unroll
            for (int pr = 0; pr < 4; pr++)
#pragma unroll
                for (int hf = 0; hf < 2; hf++) {
                    int nt = 2 * pr + hf;
                    MMAH(s[nt], qh_[ks], kfh[pr][2 * hf], kfh[pr][2 * hf + 1]);
                    MMAH(s[nt], ql_[ks], kfh[pr][2 * hf], kfh[pr][2 * hf + 1]);
                    MMAH(s[nt], qh_[ks], kfl[pr][2 * hf], kfl[pr][2 * hf + 1]);
                }
        }

        float mx0 = -1e30f, mx1 = -1e30f;
        const bool dg = (kb == last);
#pragma unroll
        for (int nt = 0; nt < 8; nt++) {
            int c0 = kb * 64 + nt * 8 + 2 * (lane & 3);
#pragma unroll
            for (int q = 0; q < 4; q++) s[nt][q] *= sc;
            if (dg) {
                if (c0     > qrow0) s[nt][0] = -1e30f;
                if (c0 + 1 > qrow0) s[nt][1] = -1e30f;
                if (c0     > qrow1) s[nt][2] = -1e30f;
                if (c0 + 1 > qrow1) s[nt][3] = -1e30f;
            }
            mx0 = fmaxf(mx0, fmaxf(s[nt][0], s[nt][1]));
            mx1 = fmaxf(mx1, fmaxf(s[nt][2], s[nt][3]));
        }
        mx0 = fmaxf(mx0, __shfl_xor_sync(0xffffffffu, mx0, 1));
        mx0 = fmaxf(mx0, __shfl_xor_sync(0xffffffffu, mx0, 2));
        mx1 = fmaxf(mx1, __shfl_xor_sync(0xffffffffu, mx1, 1));
        mx1 = fmaxf(mx1, __shfl_xor_sync(0xffffffffu, mx1, 2));

        float mn0 = fmaxf(m0, mx0), mn1 = fmaxf(m1, mx1);
        float cr0 = __expf(m0 - mn0), cr1 = __expf(m1 - mn1);
        float sum0 = 0.0f, sum1 = 0.0f;
#pragma unroll
        for (int nt = 0; nt < 8; nt++) {
            s[nt][0] = __expf(s[nt][0] - mn0);
            s[nt][1] = __expf(s[nt][1] - mn0);
            s[nt][2] = __expf(s[nt][2] - mn1);
            s[nt][3] = __expf(s[nt][3] - mn1);
            sum0 += s[nt][0] + s[nt][1];
            sum1 += s[nt][2] + s[nt][3];
        }
        sum0 += __shfl_xor_sync(0xffffffffu, sum0, 1);
        sum0 += __shfl_xor_sync(0xffffffffu, sum0, 2);
        sum1 += __shfl_xor_sync(0xffffffffu, sum1, 1);
        sum1 += __shfl_xor_sync(0xffffffffu, sum1, 2);
        l0 = l0 * cr0 + sum0;  m0 = mn0;
        l1 = l1 * cr1 + sum1;  m1 = mn1;
#pragma unroll
        for (int nt = 0; nt < 16; nt++) {
            o[nt][0] *= cr0; o[nt][1] *= cr0;
            o[nt][2] *= cr1; o[nt][3] *= cr1;
        }

#pragma unroll
        for (int ks = 0; ks < 4; ks++) {
            uint32_t p[4];
            p[0] = packh2(s[2 * ks][0],     s[2 * ks][1]);
            p[1] = packh2(s[2 * ks][2],     s[2 * ks][3]);
            p[2] = packh2(s[2 * ks + 1][0], s[2 * ks + 1][1]);
            p[3] = packh2(s[2 * ks + 1][2], s[2 * ks + 1][3]);
            uint32_t vb = (uint32_t)((ks * 16 + (lane & 15)) * AST_B + (lane >> 4) * 16);
#pragma unroll
            for (int np = 0; np < 8; np++) {
                uint32_t vfh[4], vfl[4];
                LDSM_X4_T(vfh, sVh + vb + np * 32);
                LDSM_X4_T(vfl, sVl + vb + np * 32);
                MMAH(o[2 * np],     p, vfh[0], vfh[1]);
                MMAH(o[2 * np + 1], p, vfh[2], vfh[3]);
                MMAH(o[2 * np],     p, vfl[0], vfl[1]);
                MMAH(o[2 * np + 1], p, vfl[2], vfl[3]);
            }
        }
        __syncthreads();
    }

    float i0 = 1.0f / l0, i1 = 1.0f / l1;
    size_t r0 = (size_t)(b * T_ + qb + w * 16 + (lane >> 2)) * QS_ + h * DH_ + 2 * (lane & 3);
    size_t r1 = r0 + (size_t)8 * QS_;
#pragma unroll
    for (int nt = 0; nt < 16; nt++) {
        int cc = nt * 8;
        *(float2*)&g_y[r0 + cc] = make_float2(o[nt][0] * i0, o[nt][1] * i0);
        *(float2*)&g_y[r1 + cc] = make_float2(o[nt][2] * i1, o[nt][3] * i1);
    }
}

// ----------------------------------------------------------------------------
extern "C" void kernel_launch(void* const* d_in, const int* in_sizes, int n_in,
                              void* d_out, int out_size)
{
    const float* x    = (const float*)d_in[0];
    const float* fcos = (const float*)d_in[1];
    const float* fsin = (const float*)d_in[2];
    const float* wqkv = (const float*)d_in[3];
    const float* wo   = (const float*)d_in[4];
    float* out = (float*)d_out;

    float *qkv, *yb;
    int8_t *xd1, *xd0, *wd1, *wd0, *od1, *od0, *yd1, *yd0;
    float *sx, *sw, *so, *sy;
    cudaGetSymbolAddress((void**)&qkv, g_qkv);
    cudaGetSymbolAddress((void**)&yb,  g_y);
    cudaGetSymbolAddress((void**)&xd1, g_xd1);
    cudaGetSymbolAddress((void**)&xd0, g_xd0);
    cudaGetSymbolAddress((void**)&wd1, g_wd1);
    cudaGetSymbolAddress((void**)&wd0, g_wd0);
    cudaGetSymbolAddress((void**)&od1, g_od1);
    cudaGetSymbolAddress((void**)&od0, g_od0);
    cudaGetSymbolAddress((void**)&yd1, g_yd1);
    cudaGetSymbolAddress((void**)&yd0, g_yd0);
    cudaGetSymbolAddress((void**)&sx,  g_sx);
    cudaGetSymbolAddress((void**)&sw,  g_sw);
    cudaGetSymbolAddress((void**)&so,  g_so);
    cudaGetSymbolAddress((void**)&sy,  g_sy);

    cudaFuncSetAttribute(gemm3i8_kernel,
                         cudaFuncAttributeMaxDynamicSharedMemorySize, IGSMEM);
    cudaFuncSetAttribute(attn_mma_kernel,
                         cudaFuncAttributeMaxDynamicSharedMemorySize, ASMEM);

    // 1) quantize inputs (all rows have K=4096)
    quant_kernel<<<M_,    256>>>(x,    xd1, xd0, sx);
    quant_kernel<<<QKVN_, 256>>>(wqkv, wd1, wd0, sw);
    quant_kernel<<<D_,    256>>>(wo,   od1, od0, so);

    // 2) qkv = x @ w_qkv^T  (int8 IMMA)
    gemm3i8_kernel<<<dim3(QKVN_ / 64, M_ / 128), 256, IGSMEM>>>(
        xd1, xd0, wd1, wd0, sx, sw, qkv, M_, QKVN_, D_);

    // 3) RoPE + split into head-major fp16 planes
    {
        int total = M_ * 48 * 32;
        prep_kernel<<<(total + 255) / 256, 256>>>(fcos, fsin);
    }

    // 4) flash attention -> y (fp32)
    attn_mma_kernel<<<dim3(T_ / 64, H_, B_), 128, ASMEM>>>();

    // 5) quantize y, then out = y @ wo^T
    quant_kernel<<<M_, 256>>>(yb, yd1, yd0, sy);
    gemm3i8_kernel<<<dim3(D_ / 64, M_ / 128), 256, IGSMEM>>>(
        yd1, yd0, od1, od0, sy, so, out, M_, D_, QS_);
}

// round 10
// speedup vs baseline: 2.5684x; 2.5684x over previous
#include <cuda_runtime.h>
#include <cuda_fp16.h>
#include <cstdint>

#define B_    2
#define T_    2048
#define D_    4096
#define H_    32
#define KVH_  8
#define DH_   128
#define QS_   (H_*DH_)
#define KS_   (KVH_*DH_)
#define QKVN_ (QS_ + 2*KS_)
#define M_    (B_*T_)

// Scratch
__device__ float  g_qkv[(size_t)M_ * QKVN_];
__device__ __half g_xh[(size_t)M_ * D_];
__device__ __half g_xl[(size_t)M_ * D_];
__device__ __half g_wh[(size_t)QKVN_ * D_];
__device__ __half g_wl[(size_t)QKVN_ * D_];
__device__ __half g_oh[(size_t)D_ * QS_];
__device__ __half g_ol[(size_t)D_ * QS_];
__device__ __half g_yh[(size_t)M_ * QS_];
__device__ __half g_yl[(size_t)M_ * QS_];
__device__ __half g_Qh[(size_t)M_ * QS_];
__device__ __half g_Ql[(size_t)M_ * QS_];
__device__ __half g_Kh[(size_t)M_ * KS_];
__device__ __half g_Kl[(size_t)M_ * KS_];
__device__ __half g_Vh[(size_t)M_ * KS_];
__device__ __half g_Vl[(size_t)M_ * KS_];

// ---------------------------------------------------------------------------
__device__ __forceinline__ uint32_t smem_u32(const void* p) {
    uint32_t a;
    asm("{ .reg .u64 t; cvta.to.shared.u64 t, %1; cvt.u32.u64 %0, t; }"
        : "=r"(a) : "l"(p));
    return a;
}
__device__ __forceinline__ void cpasync16(uint32_t s, const void* g) {
    asm volatile("cp.async.cg.shared.global [%0], [%1], 16;" :: "r"(s), "l"(g));
}
#define CP_COMMIT() asm volatile("cp.async.commit_group;" ::: "memory")
#define CP_WAIT(N)  asm volatile("cp.async.wait_group %0;" :: "n"(N) : "memory")

#define LDSM_X4(r, addr)                                                      \
    asm volatile("ldmatrix.sync.aligned.m8n8.x4.shared.b16 {%0,%1,%2,%3}, [%4];" \
        : "=r"((r)[0]), "=r"((r)[1]), "=r"((r)[2]), "=r"((r)[3]) : "r"(addr))
#define LDSM_X4_T(r, addr)                                                    \
    asm volatile("ldmatrix.sync.aligned.m8n8.x4.trans.shared.b16 {%0,%1,%2,%3}, [%4];" \
        : "=r"((r)[0]), "=r"((r)[1]), "=r"((r)[2]), "=r"((r)[3]) : "r"(addr))

#define MMAH(d, a, b0, b1)                                                    \
    asm volatile("mma.sync.aligned.m16n8k16.row.col.f32.f16.f16.f32 "         \
        "{%0,%1,%2,%3}, {%4,%5,%6,%7}, {%8,%9}, {%0,%1,%2,%3};"               \
        : "+f"((d)[0]), "+f"((d)[1]), "+f"((d)[2]), "+f"((d)[3])              \
        : "r"((a)[0]), "r"((a)[1]), "r"((a)[2]), "r"((a)[3]), "r"(b0), "r"(b1))

__device__ __forceinline__ uint32_t packh2(float a, float b) {
    __half2 h = __floats2half2_rn(a, b);
    return *reinterpret_cast<uint32_t*>(&h);
}

// ---------------------------------------------------------------------------
// 3xFP16 mma.sync GEMM: C = A*B^T, CTA 128x128, BK=32, 256 thr, 2 CTA/SM.
// 3-stage cp.async ring, ONE __syncthreads per chunk, XOR-swizzled smem
// (64B rows, chunk' = chunk ^ ((row>>1)&3)) — conflict-free STS/LDSM.
// ---------------------------------------------------------------------------
#define PL64   (128 * 64)          // 8192 B per plane
#define STG64  (4 * PL64)          // 32768 B per stage
#define GSMEM_ (3 * STG64)         // 98304 B

__global__ __launch_bounds__(256, 2) void gemm3h_kernel(
    const __half* __restrict__ Ah, const __half* __restrict__ Al,
    const __half* __restrict__ Bh, const __half* __restrict__ Bl,
    float* __restrict__ C, int M, int N, int K)
{
    extern __shared__ char smem[];
    const uint32_t sbase = smem_u32(smem);
    const int tid  = threadIdx.x;
    const int lane = tid & 31;
    const int wid  = tid >> 5;
    const int wm   = wid >> 1;
    const int wn   = wid & 1;

    const int bm = blockIdx.y * 128;
    const int bn = blockIdx.x * 128;
    const int nk = K >> 5;

    const __half* gp[4] = {
        Ah + (size_t)bm * K, Al + (size_t)bm * K,
        Bh + (size_t)bn * K, Bl + (size_t)bn * K };

    // loader: thread handles rows rowc and rowc+64, 16B seg each, per plane
    const int rowc = tid >> 2, seg = tid & 3;
    const int rowc2 = rowc + 64;
    const uint32_t wof1 = (uint32_t)(rowc  * 64 + ((seg ^ ((rowc  >> 1) & 3)) << 4));
    const uint32_t wof2 = (uint32_t)(rowc2 * 64 + ((seg ^ ((rowc2 >> 1) & 3)) << 4));
    const int gseg = seg * 8;   // halves offset within row

    float acc[2][8][4];
#pragma unroll
    for (int mt = 0; mt < 2; mt++)
#pragma unroll
        for (int nt = 0; nt < 8; nt++)
#pragma unroll
            for (int q = 0; q < 4; q++) acc[mt][nt][q] = 0.0f;

    // fragment address components (swizzled)
    const int rowA = lane & 15;          // within 16-row tile
    const int hiA  = lane >> 4;          // chunk half-select for A
    const int rowB = (lane & 7) + ((lane & 16) ? 8 : 0);
    const int hiB  = (lane >> 3) & 1;
    uint32_t baseA[2]; int swzA[2];
#pragma unroll
    for (int mt = 0; mt < 2; mt++) {
        int r = wm * 32 + mt * 16 + rowA;
        baseA[mt] = (uint32_t)(r * 64);
        swzA[mt]  = (r >> 1) & 3;
    }
    uint32_t baseB[4]; int swzB[4];
#pragma unroll
    for (int np = 0; np < 4; np++) {
        int r = wn * 64 + np * 16 + rowB;
        baseB[np] = (uint32_t)(r * 64);
        swzB[np]  = (r >> 1) & 3;
    }

    // prologue: prefetch chunks 0 and 1 into stages 0 and 1
#pragma unroll
    for (int pc = 0; pc < 2; pc++) {
        const uint32_t st = sbase + pc * STG64;
        const int k0 = pc << 5;
#pragma unroll
        for (int p = 0; p < 4; p++) {
            uint32_t sb = st + p * PL64;
            cpasync16(sb + wof1, gp[p] + (size_t)rowc  * K + k0 + gseg);
            cpasync16(sb + wof2, gp[p] + (size_t)rowc2 * K + k0 + gseg);
        }
        CP_COMMIT();
    }

    int s_cur = 0;
    for (int c = 0; c < nk; c++) {
        if (c + 1 < nk) { CP_WAIT(1); } else { CP_WAIT(0); }
        __syncthreads();

        if (c + 2 < nk) {
            int s_pre = s_cur + 2; if (s_pre >= 3) s_pre -= 3;
            const uint32_t st = sbase + s_pre * STG64;
            const int k0 = (c + 2) << 5;
#pragma unroll
            for (int p = 0; p < 4; p++) {
                uint32_t sb = st + p * PL64;
                cpasync16(sb + wof1, gp[p] + (size_t)rowc  * K + k0 + gseg);
                cpasync16(sb + wof2, gp[p] + (size_t)rowc2 * K + k0 + gseg);
            }
            CP_COMMIT();
        }

        const uint32_t st   = sbase + s_cur * STG64;
        const uint32_t sA_h = st;
        const uint32_t sA_l = st + PL64;
        const uint32_t sB_h = st + 2 * PL64;
        const uint32_t sB_l = st + 3 * PL64;

#pragma unroll
        for (int ks = 0; ks < 2; ks++) {
            uint32_t ah[2][4], al[2][4];
#pragma unroll
            for (int mt = 0; mt < 2; mt++) {
                uint32_t off = baseA[mt] +
                    (uint32_t)((((ks * 2 + hiA) ^ swzA[mt]) & 3) << 4);
                LDSM_X4(ah[mt], sA_h + off);
                LDSM_X4(al[mt], sA_l + off);
            }
#pragma unroll
            for (int np = 0; np < 4; np++) {
                uint32_t bh[4], bl[4];
                uint32_t off = baseB[np] +
                    (uint32_t)((((ks * 2 + hiB) ^ swzB[np]) & 3) << 4);
                LDSM_X4(bh, sB_h + off);
                LDSM_X4(bl, sB_l + off);
#pragma unroll
                for (int mt = 0; mt < 2; mt++)
#pragma unroll
                    for (int hf = 0; hf < 2; hf++) {
                        const int nt = 2 * np + hf;
                        MMAH(acc[mt][nt], ah[mt], bh[2 * hf], bh[2 * hf + 1]);
                        MMAH(acc[mt][nt], ah[mt], bl[2 * hf], bl[2 * hf + 1]);
                        MMAH(acc[mt][nt], al[mt], bh[2 * hf], bh[2 * hf + 1]);
                    }
            }
        }
        if (++s_cur == 3) s_cur = 0;
    }

#pragma unroll
    for (int mt = 0; mt < 2; mt++) {
        const int r0 = bm + wm * 32 + mt * 16 + (lane >> 2);
#pragma unroll
        for (int nt = 0; nt < 8; nt++) {
            const int col = bn + wn * 64 + nt * 8 + (lane & 3) * 2;
            *(float2*)&C[(size_t)r0 * N + col] =
                make_float2(acc[mt][nt][0], acc[mt][nt][1]);
            *(float2*)&C[(size_t)(r0 + 8) * N + col] =
                make_float2(acc[mt][nt][2], acc[mt][nt][3]);
        }
    }
}

// ---------------------------------------------------------------------------
// Split fp32 -> fp16 hi/lo
// ---------------------------------------------------------------------------
__global__ void split_kernel(const float* __restrict__ in,
                             __half* __restrict__ hi,
                             __half* __restrict__ lo, int n4)
{
    int idx = blockIdx.x * blockDim.x + threadIdx.x;
    if (idx >= n4) return;
    float4 v = ((const float4*)in)[idx];
    __half h0 = __float2half_rn(v.x), h1 = __float2half_rn(v.y);
    __half h2 = __float2half_rn(v.z), h3 = __float2half_rn(v.w);
    __half2* hp = (__half2*)(hi + (size_t)idx * 4);
    __half2* lp = (__half2*)(lo + (size_t)idx * 4);
    hp[0] = __halves2half2(h0, h1);
    hp[1] = __halves2half2(h2, h3);
    lp[0] = __floats2half2_rn(v.x - __half2float(h0), v.y - __half2float(h1));
    lp[1] = __floats2half2_rn(v.z - __half2float(h2), v.w - __half2float(h3));
}

// ---------------------------------------------------------------------------
// Prep: RoPE + split g_qkv into head-major fp16 planes
// ---------------------------------------------------------------------------
__global__ void prep_kernel(const float* __restrict__ pcos,
                            const float* __restrict__ psin)
{
    int idx = blockIdx.x * blockDim.x + threadIdx.x;
    const int total = M_ * 48 * 32;
    if (idx >= total) return;
    int q4 = idx & 31;
    int h  = (idx >> 5) % 48;
    int bt = idx / (32 * 48);
    int t  = bt & (T_ - 1);
    int b  = bt >> 11;

    float4 v = *(const float4*)&g_qkv[(size_t)bt * QKVN_ + h * DH_ + q4 * 4];
    if (h < 40) {
        float2 c = *(const float2*)&pcos[t * 64 + q4 * 2];
        float2 s = *(const float2*)&psin[t * 64 + q4 * 2];
        v = make_float4(v.x * c.x - v.y * s.x, v.x * s.x + v.y * c.x,
                        v.z * c.y - v.w * s.y, v.z * s.y + v.w * c.y);
    }
    __half *ph, *pl;
    size_t off;
    if (h < 32) {
        off = (((size_t)b * H_ + h) * T_ + t) * DH_ + q4 * 4;
        ph = g_Qh; pl = g_Ql;
    } else if (h < 40) {
        off = (((size_t)b * KVH_ + (h - 32)) * T_ + t) * DH_ + q4 * 4;
        ph = g_Kh; pl = g_Kl;
    } else {
        off = (((size_t)b * KVH_ + (h - 40)) * T_ + t) * DH_ + q4 * 4;
        ph = g_Vh; pl = g_Vl;
    }
    __half h0 = __float2half_rn(v.x), h1 = __float2half_rn(v.y);
    __half h2 = __float2half_rn(v.z), h3 = __float2half_rn(v.w);
    ((__half2*)(ph + off))[0] = __halves2half2(h0, h1);
    ((__half2*)(ph + off))[1] = __halves2half2(h2, h3);
    ((__half2*)(pl + off))[0] = __floats2half2_rn(v.x - __half2float(h0), v.y - __half2float(h1));
    ((__half2*)(pl + off))[1] = __floats2half2_rn(v.z - __half2float(h2), v.w - __half2float(h3));
}

// ---------------------------------------------------------------------------
// mma.sync flash attention (causal, GQA), writes yh/yl planes.
// ---------------------------------------------------------------------------
#define AST_B 272
#define APL_  (64 * AST_B)
#define ASMEM (4 * APL_)

__global__ __launch_bounds__(128, 2) void attn_mma_kernel()
{
    extern __shared__ char sm[];
    const uint32_t sKh = smem_u32(sm);
    const uint32_t sKl = sKh + APL_;
    const uint32_t sVh = sKh + 2 * APL_;
    const uint32_t sVl = sKh + 3 * APL_;

    const int tid = threadIdx.x, lane = tid & 31, w = tid >> 5;
    const int qb = blockIdx.x * 64;
    const int h  = blockIdx.y;
    const int b  = blockIdx.z;
    const int kh = h >> 2;

    const __half* gQh = g_Qh + ((size_t)b * H_ + h) * T_ * DH_;
    const __half* gQl = g_Ql + ((size_t)b * H_ + h) * T_ * DH_;
    const __half* gKh = g_Kh + ((size_t)b * KVH_ + kh) * T_ * DH_;
    const __half* gKl = g_Kl + ((size_t)b * KVH_ + kh) * T_ * DH_;
    const __half* gVh = g_Vh + ((size_t)b * KVH_ + kh) * T_ * DH_;
    const __half* gVl = g_Vl + ((size_t)b * KVH_ + kh) * T_ * DH_;

#pragma unroll
    for (int k = 0; k < 8; k++) {
        int id = tid + 128 * k, r = id >> 4, sg = id & 15;
        cpasync16(sKh + r * AST_B + sg * 16,
                  (const char*)(gQh + (size_t)(qb + r) * DH_) + sg * 16);
        cpasync16(sKl + r * AST_B + sg * 16,
                  (const char*)(gQl + (size_t)(qb + r) * DH_) + sg * 16);
    }
    CP_COMMIT(); CP_WAIT(0);
    __syncthreads();

    uint32_t qh_[8][4], ql_[8][4];
    {
        uint32_t base = (uint32_t)((w * 16 + (lane & 15)) * AST_B + (lane >> 4) * 16);
#pragma unroll
        for (int ks = 0; ks < 8; ks++) {
            LDSM_X4(qh_[ks], sKh + base + ks * 32);
            LDSM_X4(ql_[ks], sKl + base + ks * 32);
        }
    }
    __syncthreads();

    float o[16][4];
#pragma unroll
    for (int nt = 0; nt < 16; nt++)
#pragma unroll
        for (int q = 0; q < 4; q++) o[nt][q] = 0.0f;
    float m0 = -1e30f, m1 = -1e30f, l0 = 0.0f, l1 = 0.0f;

    const int last = qb >> 6;
    const int rowB = (lane & 7) + ((lane & 16) ? 8 : 0);
    const int colB = ((lane >> 3) & 1) * 16;
    const int qrow0 = qb + w * 16 + (lane >> 2);
    const int qrow1 = qrow0 + 8;
    const float sc = 0.08838834764831845f;

    for (int kb = 0; kb <= last; kb++) {
#pragma unroll
        for (int k = 0; k < 8; k++) {
            int id = tid + 128 * k, r = id >> 4, sg = id & 15;
            size_t grow = (size_t)(kb * 64 + r) * DH_;
            uint32_t soff = (uint32_t)(r * AST_B + sg * 16);
            cpasync16(sKh + soff, (const char*)(gKh + grow) + sg * 16);
            cpasync16(sKl + soff, (const char*)(gKl + grow) + sg * 16);
            cpasync16(sVh + soff, (const char*)(gVh + grow) + sg * 16);
            cpasync16(sVl + soff, (const char*)(gVl + grow) + sg * 16);
        }
        CP_COMMIT(); CP_WAIT(0);
        __syncthreads();

        float s[8][4];
#pragma unroll
        for (int nt = 0; nt < 8; nt++)
#pragma unroll
            for (int q = 0; q < 4; q++) s[nt][q] = 0.0f;

#pragma unroll
        for (int ks = 0; ks < 8; ks++) {
            uint32_t kfh[4][4], kfl[4][4];
#pragma unroll
            for (int pr = 0; pr < 4; pr++) {
                uint32_t off = (uint32_t)((pr * 16 + rowB) * AST_B + colB + ks * 32);
                LDSM_X4(kfh[pr], sKh + off);
                LDSM_X4(kfl[pr], sKl + off);
            }
#pragma unroll
            for (int pr = 0; pr < 4; pr++)
#pragma unroll
                for (int hf = 0; hf < 2; hf++) {
                    int nt = 2 * pr + hf;
                    MMAH(s[nt], qh_[ks], kfh[pr][2 * hf], kfh[pr][2 * hf + 1]);
                    MMAH(s[nt], ql_[ks], kfh[pr][2 * hf], kfh[pr][2 * hf + 1]);
                    MMAH(s[nt], qh_[ks], kfl[pr][2 * hf], kfl[pr][2 * hf + 1]);
                }
        }

        float mx0 = -1e30f, mx1 = -1e30f;
        const bool dg = (kb == last);
#pragma unroll
        for (int nt = 0; nt < 8; nt++) {
            int c0 = kb * 64 + nt * 8 + 2 * (lane & 3);
#pragma unroll
            for (int q = 0; q < 4; q++) s[nt][q] *= sc;
            if (dg) {
                if (c0     > qrow0) s[nt][0] = -1e30f;
                if (c0 + 1 > qrow0) s[nt][1] = -1e30f;
                if (c0     > qrow1) s[nt][2] = -1e30f;
                if (c0 + 1 > qrow1) s[nt][3] = -1e30f;
            }
            mx0 = fmaxf(mx0, fmaxf(s[nt][0], s[nt][1]));
            mx1 = fmaxf(mx1, fmaxf(s[nt][2], s[nt][3]));
        }
        mx0 = fmaxf(mx0, __shfl_xor_sync(0xffffffffu, mx0, 1));
        mx0 = fmaxf(mx0, __shfl_xor_sync(0xffffffffu, mx0, 2));
        mx1 = fmaxf(mx1, __shfl_xor_sync(0xffffffffu, mx1, 1));
        mx1 = fmaxf(mx1, __shfl_xor_sync(0xffffffffu, mx1, 2));

        float mn0 = fmaxf(m0, mx0), mn1 = fmaxf(m1, mx1);
        float cr0 = __expf(m0 - mn0), cr1 = __expf(m1 - mn1);
        float sum0 = 0.0f, sum1 = 0.0f;
#pragma unroll
        for (int nt = 0; nt < 8; nt++) {
            s[nt][0] = __expf(s[nt][0] - mn0);
            s[nt][1] = __expf(s[nt][1] - mn0);
            s[nt][2] = __expf(s[nt][2] - mn1);
            s[nt][3] = __expf(s[nt][3] - mn1);
            sum0 += s[nt][0] + s[nt][1];
            sum1 += s[nt][2] + s[nt][3];
        }
        sum0 += __shfl_xor_sync(0xffffffffu, sum0, 1);
        sum0 += __shfl_xor_sync(0xffffffffu, sum0, 2);
        sum1 += __shfl_xor_sync(0xffffffffu, sum1, 1);
        sum1 += __shfl_xor_sync(0xffffffffu, sum1, 2);
        l0 = l0 * cr0 + sum0;  m0 = mn0;
        l1 = l1 * cr1 + sum1;  m1 = mn1;
#pragma unroll
        for (int nt = 0; nt < 16; nt++) {
            o[nt][0] *= cr0; o[nt][1] *= cr0;
            o[nt][2] *= cr1; o[nt][3] *= cr1;
        }

#pragma unroll
        for (int ks = 0; ks < 4; ks++) {
            uint32_t p[4];
            p[0] = packh2(s[2 * ks][0],     s[2 * ks][1]);
            p[1] = packh2(s[2 * ks][2],     s[2 * ks][3]);
            p[2] = packh2(s[2 * ks + 1][0], s[2 * ks + 1][1]);
            p[3] = packh2(s[2 * ks + 1][2], s[2 * ks + 1][3]);
            uint32_t vb = (uint32_t)((ks * 16 + (lane & 15)) * AST_B + (lane >> 4) * 16);
#pragma unroll
            for (int np = 0; np < 8; np++) {
                uint32_t vfh[4], vfl[4];
                LDSM_X4_T(vfh, sVh + vb + np * 32);
                LDSM_X4_T(vfl, sVl + vb + np * 32);
                MMAH(o[2 * np],     p, vfh[0], vfh[1]);
                MMAH(o[2 * np + 1], p, vfh[2], vfh[3]);
                MMAH(o[2 * np],     p, vfl[0], vfl[1]);
                MMAH(o[2 * np + 1], p, vfl[2], vfl[3]);
            }
        }
        __syncthreads();
    }

    float i0 = 1.0f / l0, i1 = 1.0f / l1;
    size_t r0 = (size_t)(b * T_ + qb + w * 16 + (lane >> 2)) * QS_ + h * DH_ + 2 * (lane & 3);
    size_t r1 = r0 + (size_t)8 * QS_;
#pragma unroll
    for (int nt = 0; nt < 16; nt++) {
        int cc = nt * 8;
        float a0 = o[nt][0] * i0, a1 = o[nt][1] * i0;
        float b0 = o[nt][2] * i1, b1 = o[nt][3] * i1;
        __half ha0 = __float2half_rn(a0), ha1 = __float2half_rn(a1);
        __half hb0 = __float2half_rn(b0), hb1 = __float2half_rn(b1);
        *(__half2*)(g_yh + r0 + cc) = __halves2half2(ha0, ha1);
        *(__half2*)(g_yl + r0 + cc) =
            __floats2half2_rn(a0 - __half2float(ha0), a1 - __half2float(ha1));
        *(__half2*)(g_yh + r1 + cc) = __halves2half2(hb0, hb1);
        *(__half2*)(g_yl + r1 + cc) =
            __floats2half2_rn(b0 - __half2float(hb0), b1 - __half2float(hb1));
    }
}

// ----------------------------------------------------------------------------
extern "C" void kernel_launch(void* const* d_in, const int* in_sizes, int n_in,
                              void* d_out, int out_size)
{
    const float* x    = (const float*)d_in[0];
    const float* fcos = (const float*)d_in[1];
    const float* fsin = (const float*)d_in[2];
    const float* wqkv = (const float*)d_in[3];
    const float* wo   = (const float*)d_in[4];
    float* out = (float*)d_out;

    float* qkv = nullptr;
    __half *xh, *xl, *wh, *wl, *oh, *ol, *yh, *yl;
    cudaGetSymbolAddress((void**)&qkv, g_qkv);
    cudaGetSymbolAddress((void**)&xh,  g_xh);
    cudaGetSymbolAddress((void**)&xl,  g_xl);
    cudaGetSymbolAddress((void**)&wh,  g_wh);
    cudaGetSymbolAddress((void**)&wl,  g_wl);
    cudaGetSymbolAddress((void**)&oh,  g_oh);
    cudaGetSymbolAddress((void**)&ol,  g_ol);
    cudaGetSymbolAddress((void**)&yh,  g_yh);
    cudaGetSymbolAddress((void**)&yl,  g_yl);

    cudaFuncSetAttribute(gemm3h_kernel,
                         cudaFuncAttributeMaxDynamicSharedMemorySize, GSMEM_);
    cudaFuncSetAttribute(attn_mma_kernel,
                         cudaFuncAttributeMaxDynamicSharedMemorySize, ASMEM);

    {
        int n4 = (M_ * D_) / 4;
        split_kernel<<<(n4 + 255) / 256, 256>>>(x, xh, xl, n4);
        n4 = (QKVN_ * D_) / 4;
        split_kernel<<<(n4 + 255) / 256, 256>>>(wqkv, wh, wl, n4);
        n4 = (D_ * QS_) / 4;
        split_kernel<<<(n4 + 255) / 256, 256>>>(wo, oh, ol, n4);
    }

    gemm3h_kernel<<<dim3(QKVN_ / 128, M_ / 128), 256, GSMEM_>>>(
        xh, xl, wh, wl, qkv, M_, QKVN_, D_);

    {
        int total = M_ * 48 * 32;
        prep_kernel<<<(total + 255) / 256, 256>>>(fcos, fsin);
    }

    attn_mma_kernel<<<dim3(T_ / 64, H_, B_), 128, ASMEM>>>();

    gemm3h_kernel<<<dim3(D_ / 128, M_ / 128), 256, GSMEM_>>>(
        yh, yl, oh, ol, out, M_, D_, QS_);
}

// round 11
// speedup vs baseline: 2.6600x; 1.0356x over previous
#include <cuda_runtime.h>
#include <cuda_fp16.h>
#include <cstdint>

#define B_    2
#define T_    2048
#define D_    4096
#define H_    32
#define KVH_  8
#define DH_   128
#define QS_   (H_*DH_)
#define KS_   (KVH_*DH_)
#define QKVN_ (QS_ + 2*KS_)
#define M_    (B_*T_)

// Scratch
__device__ float  g_qkv[(size_t)M_ * QKVN_];
__device__ __half g_xh[(size_t)M_ * D_];
__device__ __half g_xl[(size_t)M_ * D_];
__device__ __half g_wh[(size_t)QKVN_ * D_];
__device__ __half g_wl[(size_t)QKVN_ * D_];
__device__ __half g_oh[(size_t)D_ * QS_];
__device__ __half g_ol[(size_t)D_ * QS_];
__device__ __half g_yh[(size_t)M_ * QS_];
__device__ __half g_yl[(size_t)M_ * QS_];
__device__ __half g_Qh[(size_t)M_ * QS_];
__device__ __half g_Ql[(size_t)M_ * QS_];
__device__ __half g_Kh[(size_t)M_ * KS_];
__device__ __half g_Kl[(size_t)M_ * KS_];
__device__ __half g_Vh[(size_t)M_ * KS_];

// ---------------------------------------------------------------------------
__device__ __forceinline__ uint32_t smem_u32(const void* p) {
    uint32_t a;
    asm("{ .reg .u64 t; cvta.to.shared.u64 t, %1; cvt.u32.u64 %0, t; }"
        : "=r"(a) : "l"(p));
    return a;
}
__device__ __forceinline__ void cpasync16(uint32_t s, const void* g) {
    asm volatile("cp.async.cg.shared.global [%0], [%1], 16;" :: "r"(s), "l"(g));
}
#define CP_COMMIT() asm volatile("cp.async.commit_group;" ::: "memory")
#define CP_WAIT(N)  asm volatile("cp.async.wait_group %0;" :: "n"(N) : "memory")

#define LDSM_X4(r, addr)                                                      \
    asm volatile("ldmatrix.sync.aligned.m8n8.x4.shared.b16 {%0,%1,%2,%3}, [%4];" \
        : "=r"((r)[0]), "=r"((r)[1]), "=r"((r)[2]), "=r"((r)[3]) : "r"(addr))
#define LDSM_X4_T(r, addr)                                                    \
    asm volatile("ldmatrix.sync.aligned.m8n8.x4.trans.shared.b16 {%0,%1,%2,%3}, [%4];" \
        : "=r"((r)[0]), "=r"((r)[1]), "=r"((r)[2]), "=r"((r)[3]) : "r"(addr))

#define MMAH(d, a, b0, b1)                                                    \
    asm volatile("mma.sync.aligned.m16n8k16.row.col.f32.f16.f16.f32 "         \
        "{%0,%1,%2,%3}, {%4,%5,%6,%7}, {%8,%9}, {%0,%1,%2,%3};"               \
        : "+f"((d)[0]), "+f"((d)[1]), "+f"((d)[2]), "+f"((d)[3])              \
        : "r"((a)[0]), "r"((a)[1]), "r"((a)[2]), "r"((a)[3]), "r"(b0), "r"(b1))

__device__ __forceinline__ uint32_t packh2(float a, float b) {
    __half2 h = __floats2half2_rn(a, b);
    return *reinterpret_cast<uint32_t*>(&h);
}

// ---------------------------------------------------------------------------
// 3xFP16 mma.sync GEMM: C = A*B^T, CTA 128x128, BK=32, 256 thr, 2 CTA/SM.
// 3-stage cp.async ring, ONE __syncthreads per chunk, XOR-swizzled smem.
// (unchanged from R10 winner)
// ---------------------------------------------------------------------------
#define PL64   (128 * 64)
#define STG64  (4 * PL64)
#define GSMEM_ (3 * STG64)

__global__ __launch_bounds__(256, 2) void gemm3h_kernel(
    const __half* __restrict__ Ah, const __half* __restrict__ Al,
    const __half* __restrict__ Bh, const __half* __restrict__ Bl,
    float* __restrict__ C, int M, int N, int K)
{
    extern __shared__ char smem[];
    const uint32_t sbase = smem_u32(smem);
    const int tid  = threadIdx.x;
    const int lane = tid & 31;
    const int wid  = tid >> 5;
    const int wm   = wid >> 1;
    const int wn   = wid & 1;

    const int bm = blockIdx.y * 128;
    const int bn = blockIdx.x * 128;
    const int nk = K >> 5;

    const __half* gp[4] = {
        Ah + (size_t)bm * K, Al + (size_t)bm * K,
        Bh + (size_t)bn * K, Bl + (size_t)bn * K };

    const int rowc = tid >> 2, seg = tid & 3;
    const int rowc2 = rowc + 64;
    const uint32_t wof1 = (uint32_t)(rowc  * 64 + ((seg ^ ((rowc  >> 1) & 3)) << 4));
    const uint32_t wof2 = (uint32_t)(rowc2 * 64 + ((seg ^ ((rowc2 >> 1) & 3)) << 4));
    const int gseg = seg * 8;

    float acc[2][8][4];
#pragma unroll
    for (int mt = 0; mt < 2; mt++)
#pragma unroll
        for (int nt = 0; nt < 8; nt++)
#pragma unroll
            for (int q = 0; q < 4; q++) acc[mt][nt][q] = 0.0f;

    const int rowA = lane & 15;
    const int hiA  = lane >> 4;
    const int rowB = (lane & 7) + ((lane & 16) ? 8 : 0);
    const int hiB  = (lane >> 3) & 1;
    uint32_t baseA[2]; int swzA[2];
#pragma unroll
    for (int mt = 0; mt < 2; mt++) {
        int r = wm * 32 + mt * 16 + rowA;
        baseA[mt] = (uint32_t)(r * 64);
        swzA[mt]  = (r >> 1) & 3;
    }
    uint32_t baseB[4]; int swzB[4];
#pragma unroll
    for (int np = 0; np < 4; np++) {
        int r = wn * 64 + np * 16 + rowB;
        baseB[np] = (uint32_t)(r * 64);
        swzB[np]  = (r >> 1) & 3;
    }

#pragma unroll
    for (int pc = 0; pc < 2; pc++) {
        const uint32_t st = sbase + pc * STG64;
        const int k0 = pc << 5;
#pragma unroll
        for (int p = 0; p < 4; p++) {
            uint32_t sb = st + p * PL64;
            cpasync16(sb + wof1, gp[p] + (size_t)rowc  * K + k0 + gseg);
            cpasync16(sb + wof2, gp[p] + (size_t)rowc2 * K + k0 + gseg);
        }
        CP_COMMIT();
    }

    int s_cur = 0;
    for (int c = 0; c < nk; c++) {
        if (c + 1 < nk) { CP_WAIT(1); } else { CP_WAIT(0); }
        __syncthreads();

        if (c + 2 < nk) {
            int s_pre = s_cur + 2; if (s_pre >= 3) s_pre -= 3;
            const uint32_t st = sbase + s_pre * STG64;
            const int k0 = (c + 2) << 5;
#pragma unroll
            for (int p = 0; p < 4; p++) {
                uint32_t sb = st + p * PL64;
                cpasync16(sb + wof1, gp[p] + (size_t)rowc  * K + k0 + gseg);
                cpasync16(sb + wof2, gp[p] + (size_t)rowc2 * K + k0 + gseg);
            }
            CP_COMMIT();
        }

        const uint32_t st   = sbase + s_cur * STG64;
        const uint32_t sA_h = st;
        const uint32_t sA_l = st + PL64;
        const uint32_t sB_h = st + 2 * PL64;
        const uint32_t sB_l = st + 3 * PL64;

#pragma unroll
        for (int ks = 0; ks < 2; ks++) {
            uint32_t ah[2][4], al[2][4];
#pragma unroll
            for (int mt = 0; mt < 2; mt++) {
                uint32_t off = baseA[mt] +
                    (uint32_t)((((ks * 2 + hiA) ^ swzA[mt]) & 3) << 4);
                LDSM_X4(ah[mt], sA_h + off);
                LDSM_X4(al[mt], sA_l + off);
            }
#pragma unroll
            for (int np = 0; np < 4; np++) {
                uint32_t bh[4], bl[4];
                uint32_t off = baseB[np] +
                    (uint32_t)((((ks * 2 + hiB) ^ swzB[np]) & 3) << 4);
                LDSM_X4(bh, sB_h + off);
                LDSM_X4(bl, sB_l + off);
#pragma unroll
                for (int mt = 0; mt < 2; mt++)
#pragma unroll
                    for (int hf = 0; hf < 2; hf++) {
                        const int nt = 2 * np + hf;
                        MMAH(acc[mt][nt], ah[mt], bh[2 * hf], bh[2 * hf + 1]);
                        MMAH(acc[mt][nt], ah[mt], bl[2 * hf], bl[2 * hf + 1]);
                        MMAH(acc[mt][nt], al[mt], bh[2 * hf], bh[2 * hf + 1]);
                    }
            }
        }
        if (++s_cur == 3) s_cur = 0;
    }

#pragma unroll
    for (int mt = 0; mt < 2; mt++) {
        const int r0 = bm + wm * 32 + mt * 16 + (lane >> 2);
#pragma unroll
        for (int nt = 0; nt < 8; nt++) {
            const int col = bn + wn * 64 + nt * 8 + (lane & 3) * 2;
            *(float2*)&C[(size_t)r0 * N + col] =
                make_float2(acc[mt][nt][0], acc[mt][nt][1]);
            *(float2*)&C[(size_t)(r0 + 8) * N + col] =
                make_float2(acc[mt][nt][2], acc[mt][nt][3]);
        }
    }
}

// ---------------------------------------------------------------------------
// Split fp32 -> fp16 hi/lo
// ---------------------------------------------------------------------------
__global__ void split_kernel(const float* __restrict__ in,
                             __half* __restrict__ hi,
                             __half* __restrict__ lo, int n4)
{
    int idx = blockIdx.x * blockDim.x + threadIdx.x;
    if (idx >= n4) return;
    float4 v = ((const float4*)in)[idx];
    __half h0 = __float2half_rn(v.x), h1 = __float2half_rn(v.y);
    __half h2 = __float2half_rn(v.z), h3 = __float2half_rn(v.w);
    __half2* hp = (__half2*)(hi + (size_t)idx * 4);
    __half2* lp = (__half2*)(lo + (size_t)idx * 4);
    hp[0] = __halves2half2(h0, h1);
    hp[1] = __halves2half2(h2, h3);
    lp[0] = __floats2half2_rn(v.x - __half2float(h0), v.y - __half2float(h1));
    lp[1] = __floats2half2_rn(v.z - __half2float(h2), v.w - __half2float(h3));
}

// ---------------------------------------------------------------------------
// Prep: RoPE + split g_qkv into head-major fp16 planes (V: hi plane only)
// ---------------------------------------------------------------------------
__global__ void prep_kernel(const float* __restrict__ pcos,
                            const float* __restrict__ psin)
{
    int idx = blockIdx.x * blockDim.x + threadIdx.x;
    const int total = M_ * 48 * 32;
    if (idx >= total) return;
    int q4 = idx & 31;
    int h  = (idx >> 5) % 48;
    int bt = idx / (32 * 48);
    int t  = bt & (T_ - 1);
    int b  = bt >> 11;

    float4 v = *(const float4*)&g_qkv[(size_t)bt * QKVN_ + h * DH_ + q4 * 4];
    if (h < 40) {
        float2 c = *(const float2*)&pcos[t * 64 + q4 * 2];
        float2 s = *(const float2*)&psin[t * 64 + q4 * 2];
        v = make_float4(v.x * c.x - v.y * s.x, v.x * s.x + v.y * c.x,
                        v.z * c.y - v.w * s.y, v.z * s.y + v.w * c.y);
    }
    __half h0 = __float2half_rn(v.x), h1 = __float2half_rn(v.y);
    __half h2 = __float2half_rn(v.z), h3 = __float2half_rn(v.w);
    if (h >= 40) {   // V: hi plane only
        size_t off = (((size_t)b * KVH_ + (h - 40)) * T_ + t) * DH_ + q4 * 4;
        ((__half2*)(g_Vh + off))[0] = __halves2half2(h0, h1);
        ((__half2*)(g_Vh + off))[1] = __halves2half2(h2, h3);
        return;
    }
    __half *ph, *pl;
    size_t off;
    if (h < 32) {
        off = (((size_t)b * H_ + h) * T_ + t) * DH_ + q4 * 4;
        ph = g_Qh; pl = g_Ql;
    } else {
        off = (((size_t)b * KVH_ + (h - 32)) * T_ + t) * DH_ + q4 * 4;
        ph = g_Kh; pl = g_Kl;
    }
    ((__half2*)(ph + off))[0] = __halves2half2(h0, h1);
    ((__half2*)(ph + off))[1] = __halves2half2(h2, h3);
    ((__half2*)(pl + off))[0] = __floats2half2_rn(v.x - __half2float(h0), v.y - __half2float(h1));
    ((__half2*)(pl + off))[1] = __floats2half2_rn(v.z - __half2float(h2), v.w - __half2float(h3));
}

// ---------------------------------------------------------------------------
// mma.sync flash attention (causal, GQA), writes yh/yl planes.
// 3 planes (Kh,Kl,Vh), 2-stage cp.async ring, one sync per key tile.
// PV correction term dropped (error budget analysis: ~2e-4 << 1e-3 gate).
// ---------------------------------------------------------------------------
#define AST_B 272
#define APL_  (64 * AST_B)      // 17408
#define ASTG  (3 * APL_)        // 52224
#define ASMEM (2 * ASTG)        // 104448

__global__ __launch_bounds__(128, 2) void attn_mma_kernel()
{
    extern __shared__ char sm[];
    const uint32_t sbase = smem_u32(sm);

    const int tid = threadIdx.x, lane = tid & 31, w = tid >> 5;
    const int qb = (int)(gridDim.x - 1 - blockIdx.x) * 64;   // largest-first
    const int h  = blockIdx.y;
    const int b  = blockIdx.z;
    const int kh = h >> 2;

    const __half* gQh = g_Qh + ((size_t)b * H_ + h) * T_ * DH_;
    const __half* gQl = g_Ql + ((size_t)b * H_ + h) * T_ * DH_;
    const __half* gKh = g_Kh + ((size_t)b * KVH_ + kh) * T_ * DH_;
    const __half* gKl = g_Kl + ((size_t)b * KVH_ + kh) * T_ * DH_;
    const __half* gVh = g_Vh + ((size_t)b * KVH_ + kh) * T_ * DH_;

    // stage Q into stage0 planes 0/1, extract frags
#pragma unroll
    for (int k = 0; k < 8; k++) {
        int id = tid + 128 * k, r = id >> 4, sg = id & 15;
        cpasync16(sbase + r * AST_B + sg * 16,
                  (const char*)(gQh + (size_t)(qb + r) * DH_) + sg * 16);
        cpasync16(sbase + APL_ + r * AST_B + sg * 16,
                  (const char*)(gQl + (size_t)(qb + r) * DH_) + sg * 16);
    }
    CP_COMMIT(); CP_WAIT(0);
    __syncthreads();

    uint32_t qh_[8][4], ql_[8][4];
    {
        uint32_t base = (uint32_t)((w * 16 + (lane & 15)) * AST_B + (lane >> 4) * 16);
#pragma unroll
        for (int ks = 0; ks < 8; ks++) {
            LDSM_X4(qh_[ks], sbase + base + ks * 32);
            LDSM_X4(ql_[ks], sbase + APL_ + base + ks * 32);
        }
    }
    __syncthreads();   // all done reading Q before stage0 is overwritten

    const int last = qb >> 6;

    // prologue: prefetch tile 0 into stage 0
#pragma unroll
    for (int k = 0; k < 8; k++) {
        int id = tid + 128 * k, r = id >> 4, sg = id & 15;
        size_t grow = (size_t)r * DH_;
        uint32_t soff = (uint32_t)(r * AST_B + sg * 16);
        cpasync16(sbase + soff,            (const char*)(gKh + grow) + sg * 16);
        cpasync16(sbase + APL_ + soff,     (const char*)(gKl + grow) + sg * 16);
        cpasync16(sbase + 2 * APL_ + soff, (const char*)(gVh + grow) + sg * 16);
    }
    CP_COMMIT();

    float o[16][4];
#pragma unroll
    for (int nt = 0; nt < 16; nt++)
#pragma unroll
        for (int q = 0; q < 4; q++) o[nt][q] = 0.0f;
    float m0 = -1e30f, m1 = -1e30f, l0 = 0.0f, l1 = 0.0f;

    const int rowB = (lane & 7) + ((lane & 16) ? 8 : 0);
    const int colB = ((lane >> 3) & 1) * 16;
    const int qrow0 = qb + w * 16 + (lane >> 2);
    const int qrow1 = qrow0 + 8;
    const float sc = 0.08838834764831845f;

    for (int kb = 0; kb <= last; kb++) {
        CP_WAIT(0);
        __syncthreads();

        const uint32_t stc = sbase + (uint32_t)(kb & 1) * ASTG;
        if (kb < last) {
            const uint32_t stn = sbase + (uint32_t)((kb + 1) & 1) * ASTG;
#pragma unroll
            for (int k = 0; k < 8; k++) {
                int id = tid + 128 * k, r = id >> 4, sg = id & 15;
                size_t grow = (size_t)((kb + 1) * 64 + r) * DH_;
                uint32_t soff = (uint32_t)(r * AST_B + sg * 16);
                cpasync16(stn + soff,            (const char*)(gKh + grow) + sg * 16);
                cpasync16(stn + APL_ + soff,     (const char*)(gKl + grow) + sg * 16);
                cpasync16(stn + 2 * APL_ + soff, (const char*)(gVh + grow) + sg * 16);
            }
            CP_COMMIT();
        }

        const uint32_t sKh = stc;
        const uint32_t sKl = stc + APL_;
        const uint32_t sVh = stc + 2 * APL_;

        float s[8][4];
#pragma unroll
        for (int nt = 0; nt < 8; nt++)
#pragma unroll
            for (int q = 0; q < 4; q++) s[nt][q] = 0.0f;

#pragma unroll
        for (int ks = 0; ks < 8; ks++) {
            uint32_t kfh[4][4], kfl[4][4];
#pragma unroll
            for (int pr = 0; pr < 4; pr++) {
                uint32_t off = (uint32_t)((pr * 16 + rowB) * AST_B + colB + ks * 32);
                LDSM_X4(kfh[pr], sKh + off);
                LDSM_X4(kfl[pr], sKl + off);
            }
#pragma unroll
            for (int pr = 0; pr < 4; pr++)
#pragma unroll
                for (int hf = 0; hf < 2; hf++) {
                    int nt = 2 * pr + hf;
                    MMAH(s[nt], qh_[ks], kfh[pr][2 * hf], kfh[pr][2 * hf + 1]);
                    MMAH(s[nt], ql_[ks], kfh[pr][2 * hf], kfh[pr][2 * hf + 1]);
                    MMAH(s[nt], qh_[ks], kfl[pr][2 * hf], kfl[pr][2 * hf + 1]);
                }
        }

        float mx0 = -1e30f, mx1 = -1e30f;
        const bool dg = (kb == last);
#pragma unroll
        for (int nt = 0; nt < 8; nt++) {
            int c0 = kb * 64 + nt * 8 + 2 * (lane & 3);
#pragma unroll
            for (int q = 0; q < 4; q++) s[nt][q] *= sc;
            if (dg) {
                if (c0     > qrow0) s[nt][0] = -1e30f;
                if (c0 + 1 > qrow0) s[nt][1] = -1e30f;
                if (c0     > qrow1) s[nt][2] = -1e30f;
                if (c0 + 1 > qrow1) s[nt][3] = -1e30f;
            }
            mx0 = fmaxf(mx0, fmaxf(s[nt][0], s[nt][1]));
            mx1 = fmaxf(mx1, fmaxf(s[nt][2], s[nt][3]));
        }
        mx0 = fmaxf(mx0, __shfl_xor_sync(0xffffffffu, mx0, 1));
        mx0 = fmaxf(mx0, __shfl_xor_sync(0xffffffffu, mx0, 2));
        mx1 = fmaxf(mx1, __shfl_xor_sync(0xffffffffu, mx1, 1));
        mx1 = fmaxf(mx1, __shfl_xor_sync(0xffffffffu, mx1, 2));

        float mn0 = fmaxf(m0, mx0), mn1 = fmaxf(m1, mx1);
        float cr0 = __expf(m0 - mn0), cr1 = __expf(m1 - mn1);
        float sum0 = 0.0f, sum1 = 0.0f;
#pragma unroll
        for (int nt = 0; nt < 8; nt++) {
            s[nt][0] = __expf(s[nt][0] - mn0);
            s[nt][1] = __expf(s[nt][1] - mn0);
            s[nt][2] = __expf(s[nt][2] - mn1);
            s[nt][3] = __expf(s[nt][3] - mn1);
            sum0 += s[nt][0] + s[nt][1];
            sum1 += s[nt][2] + s[nt][3];
        }
        sum0 += __shfl_xor_sync(0xffffffffu, sum0, 1);
        sum0 += __shfl_xor_sync(0xffffffffu, sum0, 2);
        sum1 += __shfl_xor_sync(0xffffffffu, sum1, 1);
        sum1 += __shfl_xor_sync(0xffffffffu, sum1, 2);
        l0 = l0 * cr0 + sum0;  m0 = mn0;
        l1 = l1 * cr1 + sum1;  m1 = mn1;
#pragma unroll
        for (int nt = 0; nt < 16; nt++) {
            o[nt][0] *= cr0; o[nt][1] *= cr0;
            o[nt][2] *= cr1; o[nt][3] *= cr1;
        }

#pragma unroll
        for (int ks = 0; ks < 4; ks++) {
            uint32_t p[4];
            p[0] = packh2(s[2 * ks][0],     s[2 * ks][1]);
            p[1] = packh2(s[2 * ks][2],     s[2 * ks][3]);
            p[2] = packh2(s[2 * ks + 1][0], s[2 * ks + 1][1]);
            p[3] = packh2(s[2 * ks + 1][2], s[2 * ks + 1][3]);
            uint32_t vb = (uint32_t)((ks * 16 + (lane & 15)) * AST_B + (lane >> 4) * 16);
#pragma unroll
            for (int np = 0; np < 8; np++) {
                uint32_t vfh[4];
                LDSM_X4_T(vfh, sVh + vb + np * 32);
                MMAH(o[2 * np],     p, vfh[0], vfh[1]);
                MMAH(o[2 * np + 1], p, vfh[2], vfh[3]);
            }
        }
        // no end-of-loop sync: next iteration's sync protects stage reuse
    }

    float i0 = 1.0f / l0, i1 = 1.0f / l1;
    size_t r0 = (size_t)(b * T_ + qb + w * 16 + (lane >> 2)) * QS_ + h * DH_ + 2 * (lane & 3);
    size_t r1 = r0 + (size_t)8 * QS_;
#pragma unroll
    for (int nt = 0; nt < 16; nt++) {
        int cc = nt * 8;
        float a0 = o[nt][0] * i0, a1 = o[nt][1] * i0;
        float b0 = o[nt][2] * i1, b1 = o[nt][3] * i1;
        __half ha0 = __float2half_rn(a0), ha1 = __float2half_rn(a1);
        __half hb0 = __float2half_rn(b0), hb1 = __float2half_rn(b1);
        *(__half2*)(g_yh + r0 + cc) = __halves2half2(ha0, ha1);
        *(__half2*)(g_yl + r0 + cc) =
            __floats2half2_rn(a0 - __half2float(ha0), a1 - __half2float(ha1));
        *(__half2*)(g_yh + r1 + cc) = __halves2half2(hb0, hb1);
        *(__half2*)(g_yl + r1 + cc) =
            __floats2half2_rn(b0 - __half2float(hb0), b1 - __half2float(hb1));
    }
}

// ----------------------------------------------------------------------------
extern "C" void kernel_launch(void* const* d_in, const int* in_sizes, int n_in,
                              void* d_out, int out_size)
{
    const float* x    = (const float*)d_in[0];
    const float* fcos = (const float*)d_in[1];
    const float* fsin = (const float*)d_in[2];
    const float* wqkv = (const float*)d_in[3];
    const float* wo   = (const float*)d_in[4];
    float* out = (float*)d_out;

    float* qkv = nullptr;
    __half *xh, *xl, *wh, *wl, *oh, *ol, *yh, *yl;
    cudaGetSymbolAddress((void**)&qkv, g_qkv);
    cudaGetSymbolAddress((void**)&xh,  g_xh);
    cudaGetSymbolAddress((void**)&xl,  g_xl);
    cudaGetSymbolAddress((void**)&wh,  g_wh);
    cudaGetSymbolAddress((void**)&wl,  g_wl);
    cudaGetSymbolAddress((void**)&oh,  g_oh);
    cudaGetSymbolAddress((void**)&ol,  g_ol);
    cudaGetSymbolAddress((void**)&yh,  g_yh);
    cudaGetSymbolAddress((void**)&yl,  g_yl);

    cudaFuncSetAttribute(gemm3h_kernel,
                         cudaFuncAttributeMaxDynamicSharedMemorySize, GSMEM_);
    cudaFuncSetAttribute(attn_mma_kernel,
                         cudaFuncAttributeMaxDynamicSharedMemorySize, ASMEM);

    {
        int n4 = (M_ * D_) / 4;
        split_kernel<<<(n4 + 255) / 256, 256>>>(x, xh, xl, n4);
        n4 = (QKVN_ * D_) / 4;
        split_kernel<<<(n4 + 255) / 256, 256>>>(wqkv, wh, wl, n4);
        n4 = (D_ * QS_) / 4;
        split_kernel<<<(n4 + 255) / 256, 256>>>(wo, oh, ol, n4);
    }

    gemm3h_kernel<<<dim3(QKVN_ / 128, M_ / 128), 256, GSMEM_>>>(
        xh, xl, wh, wl, qkv, M_, QKVN_, D_);

    {
        int total = M_ * 48 * 32;
        prep_kernel<<<(total + 255) / 256, 256>>>(fcos, fsin);
    }

    attn_mma_kernel<<<dim3(T_ / 64, H_, B_), 128, ASMEM>>>();

    gemm3h_kernel<<<dim3(D_ / 128, M_ / 128), 256, GSMEM_>>>(
        yh, yl, oh, ol, out, M_, D_, QS_);
}

// round 12
// speedup vs baseline: 3.5516x; 1.3352x over previous
#include <cuda_runtime.h>
#include <cuda_fp16.h>
#include <cstdint>

#define B_    2
#define T_    2048
#define D_    4096
#define H_    32
#define KVH_  8
#define DH_   128
#define QS_   (H_*DH_)
#define KS_   (KVH_*DH_)
#define QKVN_ (QS_ + 2*KS_)
#define M_    (B_*T_)

// Scratch
__device__ float  g_qkv[(size_t)M_ * QKVN_];
__device__ __half g_xh[(size_t)M_ * D_];
__device__ __half g_wh[(size_t)QKVN_ * D_];
__device__ __half g_wl[(size_t)QKVN_ * D_];
__device__ __half g_oh[(size_t)D_ * QS_];
__device__ __half g_ol[(size_t)D_ * QS_];
__device__ __half g_yh[(size_t)M_ * QS_];
__device__ __half g_Qh[(size_t)M_ * QS_];
__device__ __half g_Ql[(size_t)M_ * QS_];
__device__ __half g_Kh[(size_t)M_ * KS_];
__device__ __half g_Kl[(size_t)M_ * KS_];
__device__ __half g_Vh[(size_t)M_ * KS_];

// ---------------------------------------------------------------------------
__device__ __forceinline__ uint32_t smem_u32(const void* p) {
    uint32_t a;
    asm("{ .reg .u64 t; cvta.to.shared.u64 t, %1; cvt.u32.u64 %0, t; }"
        : "=r"(a) : "l"(p));
    return a;
}
__device__ __forceinline__ void cpasync16(uint32_t s, const void* g) {
    asm volatile("cp.async.cg.shared.global [%0], [%1], 16;" :: "r"(s), "l"(g));
}
#define CP_COMMIT() asm volatile("cp.async.commit_group;" ::: "memory")
#define CP_WAIT(N)  asm volatile("cp.async.wait_group %0;" :: "n"(N) : "memory")

#define LDSM_X4(r, addr)                                                      \
    asm volatile("ldmatrix.sync.aligned.m8n8.x4.shared.b16 {%0,%1,%2,%3}, [%4];" \
        : "=r"((r)[0]), "=r"((r)[1]), "=r"((r)[2]), "=r"((r)[3]) : "r"(addr))
#define LDSM_X4_T(r, addr)                                                    \
    asm volatile("ldmatrix.sync.aligned.m8n8.x4.trans.shared.b16 {%0,%1,%2,%3}, [%4];" \
        : "=r"((r)[0]), "=r"((r)[1]), "=r"((r)[2]), "=r"((r)[3]) : "r"(addr))

#define MMAH(d, a, b0, b1)                                                    \
    asm volatile("mma.sync.aligned.m16n8k16.row.col.f32.f16.f16.f32 "         \
        "{%0,%1,%2,%3}, {%4,%5,%6,%7}, {%8,%9}, {%0,%1,%2,%3};"               \
        : "+f"((d)[0]), "+f"((d)[1]), "+f"((d)[2]), "+f"((d)[3])              \
        : "r"((a)[0]), "r"((a)[1]), "r"((a)[2]), "r"((a)[3]), "r"(b0), "r"(b1))

__device__ __forceinline__ uint32_t packh2(float a, float b) {
    __half2 h = __floats2half2_rn(a, b);
    return *reinterpret_cast<uint32_t*>(&h);
}

// ---------------------------------------------------------------------------
// 2xFP16 mma.sync GEMM: C = A*B^T with A fp16, B = Bh+Bl split.
// CTA 128x128, BK=32, 256 thr, 2 CTA/SM, 3-stage ring, one sync/chunk,
// XOR-swizzled smem (64B rows).
// ---------------------------------------------------------------------------
#define PL64   (128 * 64)          // 8192 B per plane
#define STG3   (3 * PL64)          // 24576 B per stage (Ah,Bh,Bl)
#define GSMEM_ (3 * STG3)          // 73728 B

__global__ __launch_bounds__(256, 2) void gemm2h_kernel(
    const __half* __restrict__ Ah,
    const __half* __restrict__ Bh, const __half* __restrict__ Bl,
    float* __restrict__ C, int M, int N, int K)
{
    extern __shared__ char smem[];
    const uint32_t sbase = smem_u32(smem);
    const int tid  = threadIdx.x;
    const int lane = tid & 31;
    const int wid  = tid >> 5;
    const int wm   = wid >> 1;
    const int wn   = wid & 1;

    const int bm = blockIdx.y * 128;
    const int bn = blockIdx.x * 128;
    const int nk = K >> 5;

    const __half* gp[3] = {
        Ah + (size_t)bm * K, Bh + (size_t)bn * K, Bl + (size_t)bn * K };

    const int rowc = tid >> 2, seg = tid & 3;
    const int rowc2 = rowc + 64;
    const uint32_t wof1 = (uint32_t)(rowc  * 64 + ((seg ^ ((rowc  >> 1) & 3)) << 4));
    const uint32_t wof2 = (uint32_t)(rowc2 * 64 + ((seg ^ ((rowc2 >> 1) & 3)) << 4));
    const int gseg = seg * 8;

    float acc[2][8][4];
#pragma unroll
    for (int mt = 0; mt < 2; mt++)
#pragma unroll
        for (int nt = 0; nt < 8; nt++)
#pragma unroll
            for (int q = 0; q < 4; q++) acc[mt][nt][q] = 0.0f;

    const int rowA = lane & 15;
    const int hiA  = lane >> 4;
    const int rowB = (lane & 7) + ((lane & 16) ? 8 : 0);
    const int hiB  = (lane >> 3) & 1;
    uint32_t baseA[2]; int swzA[2];
#pragma unroll
    for (int mt = 0; mt < 2; mt++) {
        int r = wm * 32 + mt * 16 + rowA;
        baseA[mt] = (uint32_t)(r * 64);
        swzA[mt]  = (r >> 1) & 3;
    }
    uint32_t baseB[4]; int swzB[4];
#pragma unroll
    for (int np = 0; np < 4; np++) {
        int r = wn * 64 + np * 16 + rowB;
        baseB[np] = (uint32_t)(r * 64);
        swzB[np]  = (r >> 1) & 3;
    }

    // prologue: prefetch chunks 0,1
#pragma unroll
    for (int pc = 0; pc < 2; pc++) {
        const uint32_t st = sbase + pc * STG3;
        const int k0 = pc << 5;
#pragma unroll
        for (int p = 0; p < 3; p++) {
            uint32_t sb = st + p * PL64;
            cpasync16(sb + wof1, gp[p] + (size_t)rowc  * K + k0 + gseg);
            cpasync16(sb + wof2, gp[p] + (size_t)rowc2 * K + k0 + gseg);
        }
        CP_COMMIT();
    }

    int s_cur = 0;
    for (int c = 0; c < nk; c++) {
        if (c + 1 < nk) { CP_WAIT(1); } else { CP_WAIT(0); }
        __syncthreads();

        if (c + 2 < nk) {
            int s_pre = s_cur + 2; if (s_pre >= 3) s_pre -= 3;
            const uint32_t st = sbase + s_pre * STG3;
            const int k0 = (c + 2) << 5;
#pragma unroll
            for (int p = 0; p < 3; p++) {
                uint32_t sb = st + p * PL64;
                cpasync16(sb + wof1, gp[p] + (size_t)rowc  * K + k0 + gseg);
                cpasync16(sb + wof2, gp[p] + (size_t)rowc2 * K + k0 + gseg);
            }
            CP_COMMIT();
        }

        const uint32_t st   = sbase + s_cur * STG3;
        const uint32_t sA_h = st;
        const uint32_t sB_h = st + PL64;
        const uint32_t sB_l = st + 2 * PL64;

#pragma unroll
        for (int ks = 0; ks < 2; ks++) {
            uint32_t ah[2][4];
#pragma unroll
            for (int mt = 0; mt < 2; mt++) {
                uint32_t off = baseA[mt] +
                    (uint32_t)((((ks * 2 + hiA) ^ swzA[mt]) & 3) << 4);
                LDSM_X4(ah[mt], sA_h + off);
            }
#pragma unroll
            for (int np = 0; np < 4; np++) {
                uint32_t bh[4], bl[4];
                uint32_t off = baseB[np] +
                    (uint32_t)((((ks * 2 + hiB) ^ swzB[np]) & 3) << 4);
                LDSM_X4(bh, sB_h + off);
                LDSM_X4(bl, sB_l + off);
#pragma unroll
                for (int mt = 0; mt < 2; mt++)
#pragma unroll
                    for (int hf = 0; hf < 2; hf++) {
                        const int nt = 2 * np + hf;
                        MMAH(acc[mt][nt], ah[mt], bh[2 * hf], bh[2 * hf + 1]);
                        MMAH(acc[mt][nt], ah[mt], bl[2 * hf], bl[2 * hf + 1]);
                    }
            }
        }
        if (++s_cur == 3) s_cur = 0;
    }

#pragma unroll
    for (int mt = 0; mt < 2; mt++) {
        const int r0 = bm + wm * 32 + mt * 16 + (lane >> 2);
#pragma unroll
        for (int nt = 0; nt < 8; nt++) {
            const int col = bn + wn * 64 + nt * 8 + (lane & 3) * 2;
            *(float2*)&C[(size_t)r0 * N + col] =
                make_float2(acc[mt][nt][0], acc[mt][nt][1]);
            *(float2*)&C[(size_t)(r0 + 8) * N + col] =
                make_float2(acc[mt][nt][2], acc[mt][nt][3]);
        }
    }
}

// ---------------------------------------------------------------------------
// Split fp32 -> fp16 hi/lo (weights)
// ---------------------------------------------------------------------------
__global__ void split_kernel(const float* __restrict__ in,
                             __half* __restrict__ hi,
                             __half* __restrict__ lo, int n4)
{
    int idx = blockIdx.x * blockDim.x + threadIdx.x;
    if (idx >= n4) return;
    float4 v = ((const float4*)in)[idx];
    __half h0 = __float2half_rn(v.x), h1 = __float2half_rn(v.y);
    __half h2 = __float2half_rn(v.z), h3 = __float2half_rn(v.w);
    __half2* hp = (__half2*)(hi + (size_t)idx * 4);
    __half2* lp = (__half2*)(lo + (size_t)idx * 4);
    hp[0] = __halves2half2(h0, h1);
    hp[1] = __halves2half2(h2, h3);
    lp[0] = __floats2half2_rn(v.x - __half2float(h0), v.y - __half2float(h1));
    lp[1] = __floats2half2_rn(v.z - __half2float(h2), v.w - __half2float(h3));
}

// fp32 -> fp16 convert (activations: hi only)
__global__ void tohalf_kernel(const float* __restrict__ in,
                              __half* __restrict__ hi, int n4)
{
    int idx = blockIdx.x * blockDim.x + threadIdx.x;
    if (idx >= n4) return;
    float4 v = ((const float4*)in)[idx];
    __half2* hp = (__half2*)(hi + (size_t)idx * 4);
    hp[0] = __floats2half2_rn(v.x, v.y);
    hp[1] = __floats2half2_rn(v.z, v.w);
}

// ---------------------------------------------------------------------------
// Prep: RoPE + split g_qkv into head-major fp16 planes (V: hi plane only)
// ---------------------------------------------------------------------------
__global__ void prep_kernel(const float* __restrict__ pcos,
                            const float* __restrict__ psin)
{
    int idx = blockIdx.x * blockDim.x + threadIdx.x;
    const int total = M_ * 48 * 32;
    if (idx >= total) return;
    int q4 = idx & 31;
    int h  = (idx >> 5) % 48;
    int bt = idx / (32 * 48);
    int t  = bt & (T_ - 1);
    int b  = bt >> 11;

    float4 v = *(const float4*)&g_qkv[(size_t)bt * QKVN_ + h * DH_ + q4 * 4];
    if (h < 40) {
        float2 c = *(const float2*)&pcos[t * 64 + q4 * 2];
        float2 s = *(const float2*)&psin[t * 64 + q4 * 2];
        v = make_float4(v.x * c.x - v.y * s.x, v.x * s.x + v.y * c.x,
                        v.z * c.y - v.w * s.y, v.z * s.y + v.w * c.y);
    }
    __half h0 = __float2half_rn(v.x), h1 = __float2half_rn(v.y);
    __half h2 = __float2half_rn(v.z), h3 = __float2half_rn(v.w);
    if (h >= 40) {   // V: hi plane only
        size_t off = (((size_t)b * KVH_ + (h - 40)) * T_ + t) * DH_ + q4 * 4;
        ((__half2*)(g_Vh + off))[0] = __halves2half2(h0, h1);
        ((__half2*)(g_Vh + off))[1] = __halves2half2(h2, h3);
        return;
    }
    __half *ph, *pl;
    size_t off;
    if (h < 32) {
        off = (((size_t)b * H_ + h) * T_ + t) * DH_ + q4 * 4;
        ph = g_Qh; pl = g_Ql;
    } else {
        off = (((size_t)b * KVH_ + (h - 32)) * T_ + t) * DH_ + q4 * 4;
        ph = g_Kh; pl = g_Kl;
    }
    ((__half2*)(ph + off))[0] = __halves2half2(h0, h1);
    ((__half2*)(ph + off))[1] = __halves2half2(h2, h3);
    ((__half2*)(pl + off))[0] = __floats2half2_rn(v.x - __half2float(h0), v.y - __half2float(h1));
    ((__half2*)(pl + off))[1] = __floats2half2_rn(v.z - __half2float(h2), v.w - __half2float(h3));
}

// ---------------------------------------------------------------------------
// mma.sync flash attention (causal, GQA), writes yh plane.
// 3 planes (Kh,Kl,Vh), 2-stage cp.async ring, one sync per key tile.
// ---------------------------------------------------------------------------
#define AST_B 272
#define APL_  (64 * AST_B)      // 17408
#define ASTG  (3 * APL_)        // 52224
#define ASMEM (2 * ASTG)        // 104448

__global__ __launch_bounds__(128, 2) void attn_mma_kernel()
{
    extern __shared__ char sm[];
    const uint32_t sbase = smem_u32(sm);

    const int tid = threadIdx.x, lane = tid & 31, w = tid >> 5;
    const int qb = (int)(gridDim.x - 1 - blockIdx.x) * 64;
    const int h  = blockIdx.y;
    const int b  = blockIdx.z;
    const int kh = h >> 2;

    const __half* gQh = g_Qh + ((size_t)b * H_ + h) * T_ * DH_;
    const __half* gQl = g_Ql + ((size_t)b * H_ + h) * T_ * DH_;
    const __half* gKh = g_Kh + ((size_t)b * KVH_ + kh) * T_ * DH_;
    const __half* gKl = g_Kl + ((size_t)b * KVH_ + kh) * T_ * DH_;
    const __half* gVh = g_Vh + ((size_t)b * KVH_ + kh) * T_ * DH_;

#pragma unroll
    for (int k = 0; k < 8; k++) {
        int id = tid + 128 * k, r = id >> 4, sg = id & 15;
        cpasync16(sbase + r * AST_B + sg * 16,
                  (const char*)(gQh + (size_t)(qb + r) * DH_) + sg * 16);
        cpasync16(sbase + APL_ + r * AST_B + sg * 16,
                  (const char*)(gQl + (size_t)(qb + r) * DH_) + sg * 16);
    }
    CP_COMMIT(); CP_WAIT(0);
    __syncthreads();

    uint32_t qh_[8][4], ql_[8][4];
    {
        uint32_t base = (uint32_t)((w * 16 + (lane & 15)) * AST_B + (lane >> 4) * 16);
#pragma unroll
        for (int ks = 0; ks < 8; ks++) {
            LDSM_X4(qh_[ks], sbase + base + ks * 32);
            LDSM_X4(ql_[ks], sbase + APL_ + base + ks * 32);
        }
    }
    __syncthreads();

    const int last = qb >> 6;

#pragma unroll
    for (int k = 0; k < 8; k++) {
        int id = tid + 128 * k, r = id >> 4, sg = id & 15;
        size_t grow = (size_t)r * DH_;
        uint32_t soff = (uint32_t)(r * AST_B + sg * 16);
        cpasync16(sbase + soff,            (const char*)(gKh + grow) + sg * 16);
        cpasync16(sbase + APL_ + soff,     (const char*)(gKl + grow) + sg * 16);
        cpasync16(sbase + 2 * APL_ + soff, (const char*)(gVh + grow) + sg * 16);
    }
    CP_COMMIT();

    float o[16][4];
#pragma unroll
    for (int nt = 0; nt < 16; nt++)
#pragma unroll
        for (int q = 0; q < 4; q++) o[nt][q] = 0.0f;
    float m0 = -1e30f, m1 = -1e30f, l0 = 0.0f, l1 = 0.0f;

    const int rowB = (lane & 7) + ((lane & 16) ? 8 : 0);
    const int colB = ((lane >> 3) & 1) * 16;
    const int qrow0 = qb + w * 16 + (lane >> 2);
    const int qrow1 = qrow0 + 8;
    const float sc = 0.08838834764831845f;

    for (int kb = 0; kb <= last; kb++) {
        CP_WAIT(0);
        __syncthreads();

        const uint32_t stc = sbase + (uint32_t)(kb & 1) * ASTG;
        if (kb < last) {
            const uint32_t stn = sbase + (uint32_t)((kb + 1) & 1) * ASTG;
#pragma unroll
            for (int k = 0; k < 8; k++) {
                int id = tid + 128 * k, r = id >> 4, sg = id & 15;
                size_t grow = (size_t)((kb + 1) * 64 + r) * DH_;
                uint32_t soff = (uint32_t)(r * AST_B + sg * 16);
                cpasync16(stn + soff,            (const char*)(gKh + grow) + sg * 16);
                cpasync16(stn + APL_ + soff,     (const char*)(gKl + grow) + sg * 16);
                cpasync16(stn + 2 * APL_ + soff, (const char*)(gVh + grow) + sg * 16);
            }
            CP_COMMIT();
        }

        const uint32_t sKh = stc;
        const uint32_t sKl = stc + APL_;
        const uint32_t sVh = stc + 2 * APL_;

        float s[8][4];
#pragma unroll
        for (int nt = 0; nt < 8; nt++)
#pragma unroll
            for (int q = 0; q < 4; q++) s[nt][q] = 0.0f;

#pragma unroll
        for (int ks = 0; ks < 8; ks++) {
            uint32_t kfh[4][4], kfl[4][4];
#pragma unroll
            for (int pr = 0; pr < 4; pr++) {
                uint32_t off = (uint32_t)((pr * 16 + rowB) * AST_B + colB + ks * 32);
                LDSM_X4(kfh[pr], sKh + off);
                LDSM_X4(kfl[pr], sKl + off);
            }
#pragma unroll
            for (int pr = 0; pr < 4; pr++)
#pragma unroll
                for (int hf = 0; hf < 2; hf++) {
                    int nt = 2 * pr + hf;
                    MMAH(s[nt], qh_[ks], kfh[pr][2 * hf], kfh[pr][2 * hf + 1]);
                    MMAH(s[nt], ql_[ks], kfh[pr][2 * hf], kfh[pr][2 * hf + 1]);
                    MMAH(s[nt], qh_[ks], kfl[pr][2 * hf], kfl[pr][2 * hf + 1]);
                }
        }

        float mx0 = -1e30f, mx1 = -1e30f;
        const bool dg = (kb == last);
#pragma unroll
        for (int nt = 0; nt < 8; nt++) {
            int c0 = kb * 64 + nt * 8 + 2 * (lane & 3);
#pragma unroll
            for (int q = 0; q < 4; q++) s[nt][q] *= sc;
            if (dg) {
                if (c0     > qrow0) s[nt][0] = -1e30f;
                if (c0 + 1 > qrow0) s[nt][1] = -1e30f;
                if (c0     > qrow1) s[nt][2] = -1e30f;
                if (c0 + 1 > qrow1) s[nt][3] = -1e30f;
            }
            mx0 = fmaxf(mx0, fmaxf(s[nt][0], s[nt][1]));
            mx1 = fmaxf(mx1, fmaxf(s[nt][2], s[nt][3]));
        }
        mx0 = fmaxf(mx0, __shfl_xor_sync(0xffffffffu, mx0, 1));
        mx0 = fmaxf(mx0, __shfl_xor_sync(0xffffffffu, mx0, 2));
        mx1 = fmaxf(mx1, __shfl_xor_sync(0xffffffffu, mx1, 1));
        mx1 = fmaxf(mx1, __shfl_xor_sync(0xffffffffu, mx1, 2));

        float mn0 = fmaxf(m0, mx0), mn1 = fmaxf(m1, mx1);
        float cr0 = __expf(m0 - mn0), cr1 = __expf(m1 - mn1);
        float sum0 = 0.0f, sum1 = 0.0f;
#pragma unroll
        for (int nt = 0; nt < 8; nt++) {
            s[nt][0] = __expf(s[nt][0] - mn0);
            s[nt][1] = __expf(s[nt][1] - mn0);
            s[nt][2] = __expf(s[nt][2] - mn1);
            s[nt][3] = __expf(s[nt][3] - mn1);
            sum0 += s[nt][0] + s[nt][1];
            sum1 += s[nt][2] + s[nt][3];
        }
        sum0 += __shfl_xor_sync(0xffffffffu, sum0, 1);
        sum0 += __shfl_xor_sync(0xffffffffu, sum0, 2);
        sum1 += __shfl_xor_sync(0xffffffffu, sum1, 1);
        sum1 += __shfl_xor_sync(0xffffffffu, sum1, 2);
        l0 = l0 * cr0 + sum0;  m0 = mn0;
        l1 = l1 * cr1 + sum1;  m1 = mn1;
#pragma unroll
        for (int nt = 0; nt < 16; nt++) {
            o[nt][0] *= cr0; o[nt][1] *= cr0;
            o[nt][2] *= cr1; o[nt][3] *= cr1;
        }

#pragma unroll
        for (int ks = 0; ks < 4; ks++) {
            uint32_t p[4];
            p[0] = packh2(s[2 * ks][0],     s[2 * ks][1]);
            p[1] = packh2(s[2 * ks][2],     s[2 * ks][3]);
            p[2] = packh2(s[2 * ks + 1][0], s[2 * ks + 1][1]);
            p[3] = packh2(s[2 * ks + 1][2], s[2 * ks + 1][3]);
            uint32_t vb = (uint32_t)((ks * 16 + (lane & 15)) * AST_B + (lane >> 4) * 16);
#pragma unroll
            for (int np = 0; np < 8; np++) {
                uint32_t vfh[4];
                LDSM_X4_T(vfh, sVh + vb + np * 32);
                MMAH(o[2 * np],     p, vfh[0], vfh[1]);
                MMAH(o[2 * np + 1], p, vfh[2], vfh[3]);
            }
        }
    }

    float i0 = 1.0f / l0, i1 = 1.0f / l1;
    size_t r0 = (size_t)(b * T_ + qb + w * 16 + (lane >> 2)) * QS_ + h * DH_ + 2 * (lane & 3);
    size_t r1 = r0 + (size_t)8 * QS_;
#pragma unroll
    for (int nt = 0; nt < 16; nt++) {
        int cc = nt * 8;
        *(__half2*)(g_yh + r0 + cc) = __floats2half2_rn(o[nt][0] * i0, o[nt][1] * i0);
        *(__half2*)(g_yh + r1 + cc) = __floats2half2_rn(o[nt][2] * i1, o[nt][3] * i1);
    }
}

// ----------------------------------------------------------------------------
extern "C" void kernel_launch(void* const* d_in, const int* in_sizes, int n_in,
                              void* d_out, int out_size)
{
    const float* x    = (const float*)d_in[0];
    const float* fcos = (const float*)d_in[1];
    const float* fsin = (const float*)d_in[2];
    const float* wqkv = (const float*)d_in[3];
    const float* wo   = (const float*)d_in[4];
    float* out = (float*)d_out;

    float* qkv = nullptr;
    __half *xh, *wh, *wl, *oh, *ol, *yh;
    cudaGetSymbolAddress((void**)&qkv, g_qkv);
    cudaGetSymbolAddress((void**)&xh,  g_xh);
    cudaGetSymbolAddress((void**)&wh,  g_wh);
    cudaGetSymbolAddress((void**)&wl,  g_wl);
    cudaGetSymbolAddress((void**)&oh,  g_oh);
    cudaGetSymbolAddress((void**)&ol,  g_ol);
    cudaGetSymbolAddress((void**)&yh,  g_yh);

    cudaFuncSetAttribute(gemm2h_kernel,
                         cudaFuncAttributeMaxDynamicSharedMemorySize, GSMEM_);
    cudaFuncSetAttribute(attn_mma_kernel,
                         cudaFuncAttributeMaxDynamicSharedMemorySize, ASMEM);

    {
        int n4 = (M_ * D_) / 4;
        tohalf_kernel<<<(n4 + 255) / 256, 256>>>(x, xh, n4);
        n4 = (QKVN_ * D_) / 4;
        split_kernel<<<(n4 + 255) / 256, 256>>>(wqkv, wh, wl, n4);
        n4 = (D_ * QS_) / 4;
        split_kernel<<<(n4 + 255) / 256, 256>>>(wo, oh, ol, n4);
    }

    gemm2h_kernel<<<dim3(QKVN_ / 128, M_ / 128), 256, GSMEM_>>>(
        xh, wh, wl, qkv, M_, QKVN_, D_);

    {
        int total = M_ * 48 * 32;
        prep_kernel<<<(total + 255) / 256, 256>>>(fcos, fsin);
    }

    attn_mma_kernel<<<dim3(T_ / 64, H_, B_), 128, ASMEM>>>();

    gemm2h_kernel<<<dim3(D_ / 128, M_ / 128), 256, GSMEM_>>>(
        yh, oh, ol, out, M_, D_, QS_);
}

// round 13
// speedup vs baseline: 3.9489x; 1.1119x over previous
#include <cuda_runtime.h>
#include <cuda_fp16.h>
#include <cstdint>

#define B_    2
#define T_    2048
#define D_    4096
#define H_    32
#define KVH_  8
#define DH_   128
#define QS_   (H_*DH_)
#define KS_   (KVH_*DH_)
#define QKVN_ (QS_ + 2*KS_)
#define M_    (B_*T_)

// Scratch
__device__ __half g_xh[(size_t)M_ * D_];
__device__ __half g_wh[(size_t)QKVN_ * D_];
__device__ __half g_wl[(size_t)QKVN_ * D_];
__device__ __half g_oh[(size_t)D_ * QS_];
__device__ __half g_ol[(size_t)D_ * QS_];
__device__ __half g_yh[(size_t)M_ * QS_];
__device__ __half g_Qh[(size_t)M_ * QS_];
__device__ __half g_Ql[(size_t)M_ * QS_];
__device__ __half g_Kh[(size_t)M_ * KS_];
__device__ __half g_Kl[(size_t)M_ * KS_];
__device__ __half g_Vh[(size_t)M_ * KS_];

// ---------------------------------------------------------------------------
__device__ __forceinline__ uint32_t smem_u32(const void* p) {
    uint32_t a;
    asm("{ .reg .u64 t; cvta.to.shared.u64 t, %1; cvt.u32.u64 %0, t; }"
        : "=r"(a) : "l"(p));
    return a;
}
__device__ __forceinline__ void cpasync16(uint32_t s, const void* g) {
    asm volatile("cp.async.cg.shared.global [%0], [%1], 16;" :: "r"(s), "l"(g));
}
#define CP_COMMIT() asm volatile("cp.async.commit_group;" ::: "memory")
#define CP_WAIT(N)  asm volatile("cp.async.wait_group %0;" :: "n"(N) : "memory")

#define LDSM_X4(r, addr)                                                      \
    asm volatile("ldmatrix.sync.aligned.m8n8.x4.shared.b16 {%0,%1,%2,%3}, [%4];" \
        : "=r"((r)[0]), "=r"((r)[1]), "=r"((r)[2]), "=r"((r)[3]) : "r"(addr))
#define LDSM_X4_T(r, addr)                                                    \
    asm volatile("ldmatrix.sync.aligned.m8n8.x4.trans.shared.b16 {%0,%1,%2,%3}, [%4];" \
        : "=r"((r)[0]), "=r"((r)[1]), "=r"((r)[2]), "=r"((r)[3]) : "r"(addr))

#define MMAH(d, a, b0, b1)                                                    \
    asm volatile("mma.sync.aligned.m16n8k16.row.col.f32.f16.f16.f32 "         \
        "{%0,%1,%2,%3}, {%4,%5,%6,%7}, {%8,%9}, {%0,%1,%2,%3};"               \
        : "+f"((d)[0]), "+f"((d)[1]), "+f"((d)[2]), "+f"((d)[3])              \
        : "r"((a)[0]), "r"((a)[1]), "r"((a)[2]), "r"((a)[3]), "r"(b0), "r"(b1))

__device__ __forceinline__ uint32_t packh2(float a, float b) {
    __half2 h = __floats2half2_rn(a, b);
    return *reinterpret_cast<uint32_t*>(&h);
}

// ---------------------------------------------------------------------------
// 2xFP16 mma.sync GEMM: C = A*B^T (A fp16, B hi+lo). CTA 128x128, BK=64,
// 256 thr, 2 CTA/SM, 2-stage ring (one sync / 64-k chunk), SW128 swizzle
// (128B rows, chunk' = chunk ^ (row&7)).
// mode 0: store fp32 C. mode 1 (QKV GEMM): fused RoPE + fp16 split to
// head-major Q/K/V planes (CTA col tile == one head).
// ---------------------------------------------------------------------------
#define PLN_   (128 * 128)         // 16384 B per plane
#define STGN   (3 * PLN_)          // 49152 B per stage (Ah,Bh,Bl)
#define GSMEM_ (2 * STGN)          // 98304 B

__global__ __launch_bounds__(256, 2) void gemm2h_kernel(
    const __half* __restrict__ Ah,
    const __half* __restrict__ Bh, const __half* __restrict__ Bl,
    float* __restrict__ C, int M, int N, int K, int mode,
    const float* __restrict__ pcos, const float* __restrict__ psin)
{
    extern __shared__ char smem[];
    const uint32_t sbase = smem_u32(smem);
    const int tid  = threadIdx.x;
    const int lane = tid & 31;
    const int wid  = tid >> 5;
    const int wm   = wid >> 1;
    const int wn   = wid & 1;

    const int bm = blockIdx.y * 128;
    const int bn = blockIdx.x * 128;
    const int nk = K >> 6;

    const __half* gp[3] = {
        Ah + (size_t)bm * K, Bh + (size_t)bn * K, Bl + (size_t)bn * K };

    // loader: idx = j*256+tid -> row = idx>>3, seg = idx&7 (per plane, 4 iters)
    const int lrow[4] = { tid >> 3, (tid + 256) >> 3, (tid + 512) >> 3, (tid + 768) >> 3 };
    const int lseg = tid & 7;

    float acc[2][8][4];
#pragma unroll
    for (int mt = 0; mt < 2; mt++)
#pragma unroll
        for (int nt = 0; nt < 8; nt++)
#pragma unroll
            for (int q = 0; q < 4; q++) acc[mt][nt][q] = 0.0f;

    const int rowA = lane & 15;
    const int hiA  = lane >> 4;
    const int rowB = (lane & 7) + ((lane & 16) ? 8 : 0);
    const int hiB  = (lane >> 3) & 1;
    uint32_t baseA[2]; int swzA[2];
#pragma unroll
    for (int mt = 0; mt < 2; mt++) {
        int r = wm * 32 + mt * 16 + rowA;
        baseA[mt] = (uint32_t)(r * 128);
        swzA[mt]  = r & 7;
    }
    uint32_t baseB[4]; int swzB[4];
#pragma unroll
    for (int np = 0; np < 4; np++) {
        int r = wn * 64 + np * 16 + rowB;
        baseB[np] = (uint32_t)(r * 128);
        swzB[np]  = r & 7;
    }

    // prologue: prefetch chunk 0 -> stage 0
#pragma unroll
    for (int p = 0; p < 3; p++) {
        uint32_t sb = sbase + p * PLN_;
#pragma unroll
        for (int j = 0; j < 4; j++) {
            int row = lrow[j];
            uint32_t so = (uint32_t)(row * 128 + ((lseg ^ (row & 7)) << 4));
            cpasync16(sb + so, gp[p] + (size_t)row * K + lseg * 8);
        }
    }
    CP_COMMIT();

    for (int c = 0; c < nk; c++) {
        CP_WAIT(0);
        __syncthreads();

        if (c + 1 < nk) {
            const uint32_t st = sbase + ((c + 1) & 1) * STGN;
            const int k0 = (c + 1) << 6;
#pragma unroll
            for (int p = 0; p < 3; p++) {
                uint32_t sb = st + p * PLN_;
#pragma unroll
                for (int j = 0; j < 4; j++) {
                    int row = lrow[j];
                    uint32_t so = (uint32_t)(row * 128 + ((lseg ^ (row & 7)) << 4));
                    cpasync16(sb + so, gp[p] + (size_t)row * K + k0 + lseg * 8);
                }
            }
            CP_COMMIT();
        }

        const uint32_t st   = sbase + (c & 1) * STGN;
        const uint32_t sA_h = st;
        const uint32_t sB_h = st + PLN_;
        const uint32_t sB_l = st + 2 * PLN_;

#pragma unroll
        for (int ks = 0; ks < 4; ks++) {
            uint32_t ah[2][4];
#pragma unroll
            for (int mt = 0; mt < 2; mt++) {
                uint32_t off = baseA[mt] +
                    (uint32_t)((((ks * 2 + hiA) ^ swzA[mt]) & 7) << 4);
                LDSM_X4(ah[mt], sA_h + off);
            }
#pragma unroll
            for (int np = 0; np < 4; np++) {
                uint32_t bh[4], bl[4];
                uint32_t off = baseB[np] +
                    (uint32_t)((((ks * 2 + hiB) ^ swzB[np]) & 7) << 4);
                LDSM_X4(bh, sB_h + off);
                LDSM_X4(bl, sB_l + off);
#pragma unroll
                for (int mt = 0; mt < 2; mt++)
#pragma unroll
                    for (int hf = 0; hf < 2; hf++) {
                        const int nt = 2 * np + hf;
                        MMAH(acc[mt][nt], ah[mt], bh[2 * hf], bh[2 * hf + 1]);
                        MMAH(acc[mt][nt], ah[mt], bl[2 * hf], bl[2 * hf + 1]);
                    }
            }
        }
    }

    if (mode == 0) {
#pragma unroll
        for (int mt = 0; mt < 2; mt++) {
            const int r0 = bm + wm * 32 + mt * 16 + (lane >> 2);
#pragma unroll
            for (int nt = 0; nt < 8; nt++) {
                const int col = bn + wn * 64 + nt * 8 + (lane & 3) * 2;
                *(float2*)&C[(size_t)r0 * N + col] =
                    make_float2(acc[mt][nt][0], acc[mt][nt][1]);
                *(float2*)&C[(size_t)(r0 + 8) * N + col] =
                    make_float2(acc[mt][nt][2], acc[mt][nt][3]);
            }
        }
    } else {
        // fused RoPE + split: this CTA's 128 cols == head h
        const int h = bn >> 7;
#pragma unroll
        for (int mt = 0; mt < 2; mt++) {
            const int r0 = bm + wm * 32 + mt * 16 + (lane >> 2);
#pragma unroll
            for (int nt = 0; nt < 8; nt++) {
                const int cc = wn * 64 + nt * 8 + 2 * (lane & 3);  // 0..126 even
                const int i  = cc >> 1;
#pragma unroll
                for (int rr = 0; rr < 2; rr++) {
                    const int r = r0 + rr * 8;
                    const int t = r & (T_ - 1);
                    const int b = r >> 11;
                    float v0 = acc[mt][nt][rr * 2];
                    float v1 = acc[mt][nt][rr * 2 + 1];
                    if (h < 40) {
                        float cv = pcos[t * 64 + i];
                        float sv = psin[t * 64 + i];
                        float o0 = v0 * cv - v1 * sv;
                        float o1 = v0 * sv + v1 * cv;
                        v0 = o0; v1 = o1;
                    }
                    __half h0 = __float2half_rn(v0);
                    __half h1 = __float2half_rn(v1);
                    if (h < 32) {
                        size_t off = (((size_t)b * H_ + h) * T_ + t) * DH_ + cc;
                        *(__half2*)(g_Qh + off) = __halves2half2(h0, h1);
                        *(__half2*)(g_Ql + off) = __floats2half2_rn(
                            v0 - __half2float(h0), v1 - __half2float(h1));
                    } else if (h < 40) {
                        size_t off = (((size_t)b * KVH_ + (h - 32)) * T_ + t) * DH_ + cc;
                        *(__half2*)(g_Kh + off) = __halves2half2(h0, h1);
                        *(__half2*)(g_Kl + off) = __floats2half2_rn(
                            v0 - __half2float(h0), v1 - __half2float(h1));
                    } else {
                        size_t off = (((size_t)b * KVH_ + (h - 40)) * T_ + t) * DH_ + cc;
                        *(__half2*)(g_Vh + off) = __halves2half2(h0, h1);
                    }
                }
            }
        }
    }
}

// ---------------------------------------------------------------------------
// Split fp32 -> fp16 hi/lo (weights)
// ---------------------------------------------------------------------------
__global__ void split_kernel(const float* __restrict__ in,
                             __half* __restrict__ hi,
                             __half* __restrict__ lo, int n4)
{
    int idx = blockIdx.x * blockDim.x + threadIdx.x;
    if (idx >= n4) return;
    float4 v = ((const float4*)in)[idx];
    __half h0 = __float2half_rn(v.x), h1 = __float2half_rn(v.y);
    __half h2 = __float2half_rn(v.z), h3 = __float2half_rn(v.w);
    __half2* hp = (__half2*)(hi + (size_t)idx * 4);
    __half2* lp = (__half2*)(lo + (size_t)idx * 4);
    hp[0] = __halves2half2(h0, h1);
    hp[1] = __halves2half2(h2, h3);
    lp[0] = __floats2half2_rn(v.x - __half2float(h0), v.y - __half2float(h1));
    lp[1] = __floats2half2_rn(v.z - __half2float(h2), v.w - __half2float(h3));
}

// fp32 -> fp16 (activations)
__global__ void tohalf_kernel(const float* __restrict__ in,
                              __half* __restrict__ hi, int n4)
{
    int idx = blockIdx.x * blockDim.x + threadIdx.x;
    if (idx >= n4) return;
    float4 v = ((const float4*)in)[idx];
    __half2* hp = (__half2*)(hi + (size_t)idx * 4);
    hp[0] = __floats2half2_rn(v.x, v.y);
    hp[1] = __floats2half2_rn(v.z, v.w);
}

// ---------------------------------------------------------------------------
// mma.sync flash attention (causal, GQA), writes yh plane.
// 3 planes (Kh,Kl,Vh), 2-stage cp.async ring, one sync per key tile.
// (unchanged from R12 winner)
// ---------------------------------------------------------------------------
#define AST_B 272
#define APL_  (64 * AST_B)
#define ASTG  (3 * APL_)
#define ASMEM (2 * ASTG)

__global__ __launch_bounds__(128, 2) void attn_mma_kernel()
{
    extern __shared__ char sm[];
    const uint32_t sbase = smem_u32(sm);

    const int tid = threadIdx.x, lane = tid & 31, w = tid >> 5;
    const int qb = (int)(gridDim.x - 1 - blockIdx.x) * 64;
    const int h  = blockIdx.y;
    const int b  = blockIdx.z;
    const int kh = h >> 2;

    const __half* gQh = g_Qh + ((size_t)b * H_ + h) * T_ * DH_;
    const __half* gQl = g_Ql + ((size_t)b * H_ + h) * T_ * DH_;
    const __half* gKh = g_Kh + ((size_t)b * KVH_ + kh) * T_ * DH_;
    const __half* gKl = g_Kl + ((size_t)b * KVH_ + kh) * T_ * DH_;
    const __half* gVh = g_Vh + ((size_t)b * KVH_ + kh) * T_ * DH_;

#pragma unroll
    for (int k = 0; k < 8; k++) {
        int id = tid + 128 * k, r = id >> 4, sg = id & 15;
        cpasync16(sbase + r * AST_B + sg * 16,
                  (const char*)(gQh + (size_t)(qb + r) * DH_) + sg * 16);
        cpasync16(sbase + APL_ + r * AST_B + sg * 16,
                  (const char*)(gQl + (size_t)(qb + r) * DH_) + sg * 16);
    }
    CP_COMMIT(); CP_WAIT(0);
    __syncthreads();

    uint32_t qh_[8][4], ql_[8][4];
    {
        uint32_t base = (uint32_t)((w * 16 + (lane & 15)) * AST_B + (lane >> 4) * 16);
#pragma unroll
        for (int ks = 0; ks < 8; ks++) {
            LDSM_X4(qh_[ks], sbase + base + ks * 32);
            LDSM_X4(ql_[ks], sbase + APL_ + base + ks * 32);
        }
    }
    __syncthreads();

    const int last = qb >> 6;

#pragma unroll
    for (int k = 0; k < 8; k++) {
        int id = tid + 128 * k, r = id >> 4, sg = id & 15;
        size_t grow = (size_t)r * DH_;
        uint32_t soff = (uint32_t)(r * AST_B + sg * 16);
        cpasync16(sbase + soff,            (const char*)(gKh + grow) + sg * 16);
        cpasync16(sbase + APL_ + soff,     (const char*)(gKl + grow) + sg * 16);
        cpasync16(sbase + 2 * APL_ + soff, (const char*)(gVh + grow) + sg * 16);
    }
    CP_COMMIT();

    float o[16][4];
#pragma unroll
    for (int nt = 0; nt < 16; nt++)
#pragma unroll
        for (int q = 0; q < 4; q++) o[nt][q] = 0.0f;
    float m0 = -1e30f, m1 = -1e30f, l0 = 0.0f, l1 = 0.0f;

    const int rowB = (lane & 7) + ((lane & 16) ? 8 : 0);
    const int colB = ((lane >> 3) & 1) * 16;
    const int qrow0 = qb + w * 16 + (lane >> 2);
    const int qrow1 = qrow0 + 8;
    const float sc = 0.08838834764831845f;

    for (int kb = 0; kb <= last; kb++) {
        CP_WAIT(0);
        __syncthreads();

        const uint32_t stc = sbase + (uint32_t)(kb & 1) * ASTG;
        if (kb < last) {
            const uint32_t stn = sbase + (uint32_t)((kb + 1) & 1) * ASTG;
#pragma unroll
            for (int k = 0; k < 8; k++) {
                int id = tid + 128 * k, r = id >> 4, sg = id & 15;
                size_t grow = (size_t)((kb + 1) * 64 + r) * DH_;
                uint32_t soff = (uint32_t)(r * AST_B + sg * 16);
                cpasync16(stn + soff,            (const char*)(gKh + grow) + sg * 16);
                cpasync16(stn + APL_ + soff,     (const char*)(gKl + grow) + sg * 16);
                cpasync16(stn + 2 * APL_ + soff, (const char*)(gVh + grow) + sg * 16);
            }
            CP_COMMIT();
        }

        const uint32_t sKh = stc;
        const uint32_t sKl = stc + APL_;
        const uint32_t sVh = stc + 2 * APL_;

        float s[8][4];
#pragma unroll
        for (int nt = 0; nt < 8; nt++)
#pragma unroll
            for (int q = 0; q < 4; q++) s[nt][q] = 0.0f;

#pragma unroll
        for (int ks = 0; ks < 8; ks++) {
            uint32_t kfh[4][4], kfl[4][4];
#pragma unroll
            for (int pr = 0; pr < 4; pr++) {
                uint32_t off = (uint32_t)((pr * 16 + rowB) * AST_B + colB + ks * 32);
                LDSM_X4(kfh[pr], sKh + off);
                LDSM_X4(kfl[pr], sKl + off);
            }
#pragma unroll
            for (int pr = 0; pr < 4; pr++)
#pragma unroll
                for (int hf = 0; hf < 2; hf++) {
                    int nt = 2 * pr + hf;
                    MMAH(s[nt], qh_[ks], kfh[pr][2 * hf], kfh[pr][2 * hf + 1]);
                    MMAH(s[nt], ql_[ks], kfh[pr][2 * hf], kfh[pr][2 * hf + 1]);
                    MMAH(s[nt], qh_[ks], kfl[pr][2 * hf], kfl[pr][2 * hf + 1]);
                }
        }

        float mx0 = -1e30f, mx1 = -1e30f;
        const bool dg = (kb == last);
#pragma unroll
        for (int nt = 0; nt < 8; nt++) {
            int c0 = kb * 64 + nt * 8 + 2 * (lane & 3);
#pragma unroll
            for (int q = 0; q < 4; q++) s[nt][q] *= sc;
            if (dg) {
                if (c0     > qrow0) s[nt][0] = -1e30f;
                if (c0 + 1 > qrow0) s[nt][1] = -1e30f;
                if (c0     > qrow1) s[nt][2] = -1e30f;
                if (c0 + 1 > qrow1) s[nt][3] = -1e30f;
            }
            mx0 = fmaxf(mx0, fmaxf(s[nt][0], s[nt][1]));
            mx1 = fmaxf(mx1, fmaxf(s[nt][2], s[nt][3]));
        }
        mx0 = fmaxf(mx0, __shfl_xor_sync(0xffffffffu, mx0, 1));
        mx0 = fmaxf(mx0, __shfl_xor_sync(0xffffffffu, mx0, 2));
        mx1 = fmaxf(mx1, __shfl_xor_sync(0xffffffffu, mx1, 1));
        mx1 = fmaxf(mx1, __shfl_xor_sync(0xffffffffu, mx1, 2));

        float mn0 = fmaxf(m0, mx0), mn1 = fmaxf(m1, mx1);
        float cr0 = __expf(m0 - mn0), cr1 = __expf(m1 - mn1);
        float sum0 = 0.0f, sum1 = 0.0f;
#pragma unroll
        for (int nt = 0; nt < 8; nt++) {
            s[nt][0] = __expf(s[nt][0] - mn0);
            s[nt][1] = __expf(s[nt][1] - mn0);
            s[nt][2] = __expf(s[nt][2] - mn1);
            s[nt][3] = __expf(s[nt][3] - mn1);
            sum0 += s[nt][0] + s[nt][1];
            sum1 += s[nt][2] + s[nt][3];
        }
        sum0 += __shfl_xor_sync(0xffffffffu, sum0, 1);
        sum0 += __shfl_xor_sync(0xffffffffu, sum0, 2);
        sum1 += __shfl_xor_sync(0xffffffffu, sum1, 1);
        sum1 += __shfl_xor_sync(0xffffffffu, sum1, 2);
        l0 = l0 * cr0 + sum0;  m0 = mn0;
        l1 = l1 * cr1 + sum1;  m1 = mn1;
#pragma unroll
        for (int nt = 0; nt < 16; nt++) {
            o[nt][0] *= cr0; o[nt][1] *= cr0;
            o[nt][2] *= cr1; o[nt][3] *= cr1;
        }

#pragma unroll
        for (int ks = 0; ks < 4; ks++) {
            uint32_t p[4];
            p[0] = packh2(s[2 * ks][0],     s[2 * ks][1]);
            p[1] = packh2(s[2 * ks][2],     s[2 * ks][3]);
            p[2] = packh2(s[2 * ks + 1][0], s[2 * ks + 1][1]);
            p[3] = packh2(s[2 * ks + 1][2], s[2 * ks + 1][3]);
            uint32_t vb = (uint32_t)((ks * 16 + (lane & 15)) * AST_B + (lane >> 4) * 16);
#pragma unroll
            for (int np = 0; np < 8; np++) {
                uint32_t vfh[4];
                LDSM_X4_T(vfh, sVh + vb + np * 32);
                MMAH(o[2 * np],     p, vfh[0], vfh[1]);
                MMAH(o[2 * np + 1], p, vfh[2], vfh[3]);
            }
        }
    }

    float i0 = 1.0f / l0, i1 = 1.0f / l1;
    size_t r0 = (size_t)(b * T_ + qb + w * 16 + (lane >> 2)) * QS_ + h * DH_ + 2 * (lane & 3);
    size_t r1 = r0 + (size_t)8 * QS_;
#pragma unroll
    for (int nt = 0; nt < 16; nt++) {
        int cc = nt * 8;
        *(__half2*)(g_yh + r0 + cc) = __floats2half2_rn(o[nt][0] * i0, o[nt][1] * i0);
        *(__half2*)(g_yh + r1 + cc) = __floats2half2_rn(o[nt][2] * i1, o[nt][3] * i1);
    }
}

// ----------------------------------------------------------------------------
extern "C" void kernel_launch(void* const* d_in, const int* in_sizes, int n_in,
                              void* d_out, int out_size)
{
    const float* x    = (const float*)d_in[0];
    const float* fcos = (const float*)d_in[1];
    const float* fsin = (const float*)d_in[2];
    const float* wqkv = (const float*)d_in[3];
    const float* wo   = (const float*)d_in[4];
    float* out = (float*)d_out;

    __half *xh, *wh, *wl, *oh, *ol, *yh;
    cudaGetSymbolAddress((void**)&xh,  g_xh);
    cudaGetSymbolAddress((void**)&wh,  g_wh);
    cudaGetSymbolAddress((void**)&wl,  g_wl);
    cudaGetSymbolAddress((void**)&oh,  g_oh);
    cudaGetSymbolAddress((void**)&ol,  g_ol);
    cudaGetSymbolAddress((void**)&yh,  g_yh);

    cudaFuncSetAttribute(gemm2h_kernel,
                         cudaFuncAttributeMaxDynamicSharedMemorySize, GSMEM_);
    cudaFuncSetAttribute(attn_mma_kernel,
                         cudaFuncAttributeMaxDynamicSharedMemorySize, ASMEM);

    {
        int n4 = (M_ * D_) / 4;
        tohalf_kernel<<<(n4 + 255) / 256, 256>>>(x, xh, n4);
        n4 = (QKVN_ * D_) / 4;
        split_kernel<<<(n4 + 255) / 256, 256>>>(wqkv, wh, wl, n4);
        n4 = (D_ * QS_) / 4;
        split_kernel<<<(n4 + 255) / 256, 256>>>(wo, oh, ol, n4);
    }

    // QKV GEMM with fused RoPE + split epilogue (mode 1)
    gemm2h_kernel<<<dim3(QKVN_ / 128, M_ / 128), 256, GSMEM_>>>(
        xh, wh, wl, nullptr, M_, QKVN_, D_, 1, fcos, fsin);

    attn_mma_kernel<<<dim3(T_ / 64, H_, B_), 128, ASMEM>>>();

    // output GEMM (mode 0)
    gemm2h_kernel<<<dim3(D_ / 128, M_ / 128), 256, GSMEM_>>>(
        yh, oh, ol, out, M_, D_, QS_, 0, nullptr, nullptr);
}

// round 14
// speedup vs baseline: 5.8544x; 1.4825x over previous
#include <cuda_runtime.h>
#include <cuda_fp16.h>
#include <cstdint>

#define B_    2
#define T_    2048
#define D_    4096
#define H_    32
#define KVH_  8
#define DH_   128
#define QS_   (H_*DH_)
#define KS_   (KVH_*DH_)
#define QKVN_ (QS_ + 2*KS_)
#define M_    (B_*T_)

// Scratch
__device__ __half g_xh[(size_t)M_ * D_];
__device__ __half g_wh[(size_t)QKVN_ * D_];
__device__ __half g_oh[(size_t)D_ * QS_];
__device__ __half g_yh[(size_t)M_ * QS_];
__device__ __half g_Qh[(size_t)M_ * QS_];
__device__ __half g_Ql[(size_t)M_ * QS_];
__device__ __half g_Kh[(size_t)M_ * KS_];
__device__ __half g_Kl[(size_t)M_ * KS_];
__device__ __half g_Vh[(size_t)M_ * KS_];

// ---------------------------------------------------------------------------
__device__ __forceinline__ uint32_t smem_u32(const void* p) {
    uint32_t a;
    asm("{ .reg .u64 t; cvta.to.shared.u64 t, %1; cvt.u32.u64 %0, t; }"
        : "=r"(a) : "l"(p));
    return a;
}
__device__ __forceinline__ void cpasync16(uint32_t s, const void* g) {
    asm volatile("cp.async.cg.shared.global [%0], [%1], 16;" :: "r"(s), "l"(g));
}
#define CP_COMMIT() asm volatile("cp.async.commit_group;" ::: "memory")
#define CP_WAIT(N)  asm volatile("cp.async.wait_group %0;" :: "n"(N) : "memory")

#define LDSM_X4(r, addr)                                                      \
    asm volatile("ldmatrix.sync.aligned.m8n8.x4.shared.b16 {%0,%1,%2,%3}, [%4];" \
        : "=r"((r)[0]), "=r"((r)[1]), "=r"((r)[2]), "=r"((r)[3]) : "r"(addr))
#define LDSM_X4_T(r, addr)                                                    \
    asm volatile("ldmatrix.sync.aligned.m8n8.x4.trans.shared.b16 {%0,%1,%2,%3}, [%4];" \
        : "=r"((r)[0]), "=r"((r)[1]), "=r"((r)[2]), "=r"((r)[3]) : "r"(addr))

#define MMAH(d, a, b0, b1)                                                    \
    asm volatile("mma.sync.aligned.m16n8k16.row.col.f32.f16.f16.f32 "         \
        "{%0,%1,%2,%3}, {%4,%5,%6,%7}, {%8,%9}, {%0,%1,%2,%3};"               \
        : "+f"((d)[0]), "+f"((d)[1]), "+f"((d)[2]), "+f"((d)[3])              \
        : "r"((a)[0]), "r"((a)[1]), "r"((a)[2]), "r"((a)[3]), "r"(b0), "r"(b1))

__device__ __forceinline__ uint32_t packh2(float a, float b) {
    __half2 h = __floats2half2_rn(a, b);
    return *reinterpret_cast<uint32_t*>(&h);
}

// ---------------------------------------------------------------------------
// FP16 mma.sync GEMM: C = A*B^T. CTA 128x128, BK=64, 256 thr, 2 CTA/SM,
// 2-stage ring (one sync / 64-k chunk), SW128 swizzle (128B rows,
// chunk' = chunk ^ (row&7)).
// mode 0: fp32 C. mode 1 (QKV): fused RoPE + fp16 split to head-major planes.
// ---------------------------------------------------------------------------
#define PLN_   (128 * 128)         // 16384 B per plane
#define STGN   (2 * PLN_)          // 32768 B per stage (Ah,Bh)
#define GSMEM_ (2 * STGN)          // 65536 B

__global__ __launch_bounds__(256, 2) void gemm1h_kernel(
    const __half* __restrict__ Ah, const __half* __restrict__ Bh,
    float* __restrict__ C, int M, int N, int K, int mode,
    const float* __restrict__ pcos, const float* __restrict__ psin)
{
    extern __shared__ char smem[];
    const uint32_t sbase = smem_u32(smem);
    const int tid  = threadIdx.x;
    const int lane = tid & 31;
    const int wid  = tid >> 5;
    const int wm   = wid >> 1;
    const int wn   = wid & 1;

    const int bm = blockIdx.y * 128;
    const int bn = blockIdx.x * 128;
    const int nk = K >> 6;

    const __half* gp[2] = { Ah + (size_t)bm * K, Bh + (size_t)bn * K };

    const int lrow[4] = { tid >> 3, (tid + 256) >> 3, (tid + 512) >> 3, (tid + 768) >> 3 };
    const int lseg = tid & 7;

    float acc[2][8][4];
#pragma unroll
    for (int mt = 0; mt < 2; mt++)
#pragma unroll
        for (int nt = 0; nt < 8; nt++)
#pragma unroll
            for (int q = 0; q < 4; q++) acc[mt][nt][q] = 0.0f;

    const int rowA = lane & 15;
    const int hiA  = lane >> 4;
    const int rowB = (lane & 7) + ((lane & 16) ? 8 : 0);
    const int hiB  = (lane >> 3) & 1;
    uint32_t baseA[2]; int swzA[2];
#pragma unroll
    for (int mt = 0; mt < 2; mt++) {
        int r = wm * 32 + mt * 16 + rowA;
        baseA[mt] = (uint32_t)(r * 128);
        swzA[mt]  = r & 7;
    }
    uint32_t baseB[4]; int swzB[4];
#pragma unroll
    for (int np = 0; np < 4; np++) {
        int r = wn * 64 + np * 16 + rowB;
        baseB[np] = (uint32_t)(r * 128);
        swzB[np]  = r & 7;
    }

    // prologue: prefetch chunk 0 -> stage 0
#pragma unroll
    for (int p = 0; p < 2; p++) {
        uint32_t sb = sbase + p * PLN_;
#pragma unroll
        for (int j = 0; j < 4; j++) {
            int row = lrow[j];
            uint32_t so = (uint32_t)(row * 128 + ((lseg ^ (row & 7)) << 4));
            cpasync16(sb + so, gp[p] + (size_t)row * K + lseg * 8);
        }
    }
    CP_COMMIT();

    for (int c = 0; c < nk; c++) {
        CP_WAIT(0);
        __syncthreads();

        if (c + 1 < nk) {
            const uint32_t st = sbase + ((c + 1) & 1) * STGN;
            const int k0 = (c + 1) << 6;
#pragma unroll
            for (int p = 0; p < 2; p++) {
                uint32_t sb = st + p * PLN_;
#pragma unroll
                for (int j = 0; j < 4; j++) {
                    int row = lrow[j];
                    uint32_t so = (uint32_t)(row * 128 + ((lseg ^ (row & 7)) << 4));
                    cpasync16(sb + so, gp[p] + (size_t)row * K + k0 + lseg * 8);
                }
            }
            CP_COMMIT();
        }

        const uint32_t st   = sbase + (c & 1) * STGN;
        const uint32_t sA_h = st;
        const uint32_t sB_h = st + PLN_;

#pragma unroll
        for (int ks = 0; ks < 4; ks++) {
            uint32_t ah[2][4];
#pragma unroll
            for (int mt = 0; mt < 2; mt++) {
                uint32_t off = baseA[mt] +
                    (uint32_t)((((ks * 2 + hiA) ^ swzA[mt]) & 7) << 4);
                LDSM_X4(ah[mt], sA_h + off);
            }
#pragma unroll
            for (int np = 0; np < 4; np++) {
                uint32_t bh[4];
                uint32_t off = baseB[np] +
                    (uint32_t)((((ks * 2 + hiB) ^ swzB[np]) & 7) << 4);
                LDSM_X4(bh, sB_h + off);
#pragma unroll
                for (int mt = 0; mt < 2; mt++)
#pragma unroll
                    for (int hf = 0; hf < 2; hf++)
                        MMAH(acc[mt][2 * np + hf], ah[mt], bh[2 * hf], bh[2 * hf + 1]);
            }
        }
    }

    if (mode == 0) {
#pragma unroll
        for (int mt = 0; mt < 2; mt++) {
            const int r0 = bm + wm * 32 + mt * 16 + (lane >> 2);
#pragma unroll
            for (int nt = 0; nt < 8; nt++) {
                const int col = bn + wn * 64 + nt * 8 + (lane & 3) * 2;
                *(float2*)&C[(size_t)r0 * N + col] =
                    make_float2(acc[mt][nt][0], acc[mt][nt][1]);
                *(float2*)&C[(size_t)(r0 + 8) * N + col] =
                    make_float2(acc[mt][nt][2], acc[mt][nt][3]);
            }
        }
    } else {
        // fused RoPE + split: this CTA's 128 cols == head h
        const int h = bn >> 7;
#pragma unroll
        for (int mt = 0; mt < 2; mt++) {
            const int r0 = bm + wm * 32 + mt * 16 + (lane >> 2);
#pragma unroll
            for (int nt = 0; nt < 8; nt++) {
                const int cc = wn * 64 + nt * 8 + 2 * (lane & 3);
                const int i  = cc >> 1;
#pragma unroll
                for (int rr = 0; rr < 2; rr++) {
                    const int r = r0 + rr * 8;
                    const int t = r & (T_ - 1);
                    const int b = r >> 11;
                    float v0 = acc[mt][nt][rr * 2];
                    float v1 = acc[mt][nt][rr * 2 + 1];
                    if (h < 40) {
                        float cv = pcos[t * 64 + i];
                        float sv = psin[t * 64 + i];
                        float o0 = v0 * cv - v1 * sv;
                        float o1 = v0 * sv + v1 * cv;
                        v0 = o0; v1 = o1;
                    }
                    __half h0 = __float2half_rn(v0);
                    __half h1 = __float2half_rn(v1);
                    if (h < 32) {
                        size_t off = (((size_t)b * H_ + h) * T_ + t) * DH_ + cc;
                        *(__half2*)(g_Qh + off) = __halves2half2(h0, h1);
                        *(__half2*)(g_Ql + off) = __floats2half2_rn(
                            v0 - __half2float(h0), v1 - __half2float(h1));
                    } else if (h < 40) {
                        size_t off = (((size_t)b * KVH_ + (h - 32)) * T_ + t) * DH_ + cc;
                        *(__half2*)(g_Kh + off) = __halves2half2(h0, h1);
                        *(__half2*)(g_Kl + off) = __floats2half2_rn(
                            v0 - __half2float(h0), v1 - __half2float(h1));
                    } else {
                        size_t off = (((size_t)b * KVH_ + (h - 40)) * T_ + t) * DH_ + cc;
                        *(__half2*)(g_Vh + off) = __halves2half2(h0, h1);
                    }
                }
            }
        }
    }
}

// fp32 -> fp16
__global__ void tohalf_kernel(const float* __restrict__ in,
                              __half* __restrict__ hi, int n4)
{
    int idx = blockIdx.x * blockDim.x + threadIdx.x;
    if (idx >= n4) return;
    float4 v = ((const float4*)in)[idx];
    __half2* hp = (__half2*)(hi + (size_t)idx * 4);
    hp[0] = __floats2half2_rn(v.x, v.y);
    hp[1] = __floats2half2_rn(v.z, v.w);
}

// ---------------------------------------------------------------------------
// mma.sync flash attention (causal, GQA), writes yh plane.
// 3 planes (Kh,Kl,Vh), 2-stage cp.async ring, one sync per key tile.
// (unchanged from R12/R13 winner)
// ---------------------------------------------------------------------------
#define AST_B 272
#define APL_  (64 * AST_B)
#define ASTG  (3 * APL_)
#define ASMEM (2 * ASTG)

__global__ __launch_bounds__(128, 2) void attn_mma_kernel()
{
    extern __shared__ char sm[];
    const uint32_t sbase = smem_u32(sm);

    const int tid = threadIdx.x, lane = tid & 31, w = tid >> 5;
    const int qb = (int)(gridDim.x - 1 - blockIdx.x) * 64;
    const int h  = blockIdx.y;
    const int b  = blockIdx.z;
    const int kh = h >> 2;

    const __half* gQh = g_Qh + ((size_t)b * H_ + h) * T_ * DH_;
    const __half* gQl = g_Ql + ((size_t)b * H_ + h) * T_ * DH_;
    const __half* gKh = g_Kh + ((size_t)b * KVH_ + kh) * T_ * DH_;
    const __half* gKl = g_Kl + ((size_t)b * KVH_ + kh) * T_ * DH_;
    const __half* gVh = g_Vh + ((size_t)b * KVH_ + kh) * T_ * DH_;

#pragma unroll
    for (int k = 0; k < 8; k++) {
        int id = tid + 128 * k, r = id >> 4, sg = id & 15;
        cpasync16(sbase + r * AST_B + sg * 16,
                  (const char*)(gQh + (size_t)(qb + r) * DH_) + sg * 16);
        cpasync16(sbase + APL_ + r * AST_B + sg * 16,
                  (const char*)(gQl + (size_t)(qb + r) * DH_) + sg * 16);
    }
    CP_COMMIT(); CP_WAIT(0);
    __syncthreads();

    uint32_t qh_[8][4], ql_[8][4];
    {
        uint32_t base = (uint32_t)((w * 16 + (lane & 15)) * AST_B + (lane >> 4) * 16);
#pragma unroll
        for (int ks = 0; ks < 8; ks++) {
            LDSM_X4(qh_[ks], sbase + base + ks * 32);
            LDSM_X4(ql_[ks], sbase + APL_ + base + ks * 32);
        }
    }
    __syncthreads();

    const int last = qb >> 6;

#pragma unroll
    for (int k = 0; k < 8; k++) {
        int id = tid + 128 * k, r = id >> 4, sg = id & 15;
        size_t grow = (size_t)r * DH_;
        uint32_t soff = (uint32_t)(r * AST_B + sg * 16);
        cpasync16(sbase + soff,            (const char*)(gKh + grow) + sg * 16);
        cpasync16(sbase + APL_ + soff,     (const char*)(gKl + grow) + sg * 16);
        cpasync16(sbase + 2 * APL_ + soff, (const char*)(gVh + grow) + sg * 16);
    }
    CP_COMMIT();

    float o[16][4];
#pragma unroll
    for (int nt = 0; nt < 16; nt++)
#pragma unroll
        for (int q = 0; q < 4; q++) o[nt][q] = 0.0f;
    float m0 = -1e30f, m1 = -1e30f, l0 = 0.0f, l1 = 0.0f;

    const int rowB = (lane & 7) + ((lane & 16) ? 8 : 0);
    const int colB = ((lane >> 3) & 1) * 16;
    const int qrow0 = qb + w * 16 + (lane >> 2);
    const int qrow1 = qrow0 + 8;
    const float sc = 0.08838834764831845f;

    for (int kb = 0; kb <= last; kb++) {
        CP_WAIT(0);
        __syncthreads();

        const uint32_t stc = sbase + (uint32_t)(kb & 1) * ASTG;
        if (kb < last) {
            const uint32_t stn = sbase + (uint32_t)((kb + 1) & 1) * ASTG;
#pragma unroll
            for (int k = 0; k < 8; k++) {
                int id = tid + 128 * k, r = id >> 4, sg = id & 15;
                size_t grow = (size_t)((kb + 1) * 64 + r) * DH_;
                uint32_t soff = (uint32_t)(r * AST_B + sg * 16);
                cpasync16(stn + soff,            (const char*)(gKh + grow) + sg * 16);
                cpasync16(stn + APL_ + soff,     (const char*)(gKl + grow) + sg * 16);
                cpasync16(stn + 2 * APL_ + soff, (const char*)(gVh + grow) + sg * 16);
            }
            CP_COMMIT();
        }

        const uint32_t sKh = stc;
        const uint32_t sKl = stc + APL_;
        const uint32_t sVh = stc + 2 * APL_;

        float s[8][4];
#pragma unroll
        for (int nt = 0; nt < 8; nt++)
#pragma unroll
            for (int q = 0; q < 4; q++) s[nt][q] = 0.0f;

#pragma unroll
        for (int ks = 0; ks < 8; ks++) {
            uint32_t kfh[4][4], kfl[4][4];
#pragma unroll
            for (int pr = 0; pr < 4; pr++) {
                uint32_t off = (uint32_t)((pr * 16 + rowB) * AST_B + colB + ks * 32);
                LDSM_X4(kfh[pr], sKh + off);
                LDSM_X4(kfl[pr], sKl + off);
            }
#pragma unroll
            for (int pr = 0; pr < 4; pr++)
#pragma unroll
                for (int hf = 0; hf < 2; hf++) {
                    int nt = 2 * pr + hf;
                    MMAH(s[nt], qh_[ks], kfh[pr][2 * hf], kfh[pr][2 * hf + 1]);
                    MMAH(s[nt], ql_[ks], kfh[pr][2 * hf], kfh[pr][2 * hf + 1]);
                    MMAH(s[nt], qh_[ks], kfl[pr][2 * hf], kfl[pr][2 * hf + 1]);
                }
        }

        float mx0 = -1e30f, mx1 = -1e30f;
        const bool dg = (kb == last);
#pragma unroll
        for (int nt = 0; nt < 8; nt++) {
            int c0 = kb * 64 + nt * 8 + 2 * (lane & 3);
#pragma unroll
            for (int q = 0; q < 4; q++) s[nt][q] *= sc;
            if (dg) {
                if (c0     > qrow0) s[nt][0] = -1e30f;
                if (c0 + 1 > qrow0) s[nt][1] = -1e30f;
                if (c0     > qrow1) s[nt][2] = -1e30f;
                if (c0 + 1 > qrow1) s[nt][3] = -1e30f;
            }
            mx0 = fmaxf(mx0, fmaxf(s[nt][0], s[nt][1]));
            mx1 = fmaxf(mx1, fmaxf(s[nt][2], s[nt][3]));
        }
        mx0 = fmaxf(mx0, __shfl_xor_sync(0xffffffffu, mx0, 1));
        mx0 = fmaxf(mx0, __shfl_xor_sync(0xffffffffu, mx0, 2));
        mx1 = fmaxf(mx1, __shfl_xor_sync(0xffffffffu, mx1, 1));
        mx1 = fmaxf(mx1, __shfl_xor_sync(0xffffffffu, mx1, 2));

        float mn0 = fmaxf(m0, mx0), mn1 = fmaxf(m1, mx1);
        float cr0 = __expf(m0 - mn0), cr1 = __expf(m1 - mn1);
        float sum0 = 0.0f, sum1 = 0.0f;
#pragma unroll
        for (int nt = 0; nt < 8; nt++) {
            s[nt][0] = __expf(s[nt][0] - mn0);
            s[nt][1] = __expf(s[nt][1] - mn0);
            s[nt][2] = __expf(s[nt][2] - mn1);
            s[nt][3] = __expf(s[nt][3] - mn1);
            sum0 += s[nt][0] + s[nt][1];
            sum1 += s[nt][2] + s[nt][3];
        }
        sum0 += __shfl_xor_sync(0xffffffffu, sum0, 1);
        sum0 += __shfl_xor_sync(0xffffffffu, sum0, 2);
        sum1 += __shfl_xor_sync(0xffffffffu, sum1, 1);
        sum1 += __shfl_xor_sync(0xffffffffu, sum1, 2);
        l0 = l0 * cr0 + sum0;  m0 = mn0;
        l1 = l1 * cr1 + sum1;  m1 = mn1;
#pragma unroll
        for (int nt = 0; nt < 16; nt++) {
            o[nt][0] *= cr0; o[nt][1] *= cr0;
            o[nt][2] *= cr1; o[nt][3] *= cr1;
        }

#pragma unroll
        for (int ks = 0; ks < 4; ks++) {
            uint32_t p[4];
            p[0] = packh2(s[2 * ks][0],     s[2 * ks][1]);
            p[1] = packh2(s[2 * ks][2],     s[2 * ks][3]);
            p[2] = packh2(s[2 * ks + 1][0], s[2 * ks + 1][1]);
            p[3] = packh2(s[2 * ks + 1][2], s[2 * ks + 1][3]);
            uint32_t vb = (uint32_t)((ks * 16 + (lane & 15)) * AST_B + (lane >> 4) * 16);
#pragma unroll
            for (int np = 0; np < 8; np++) {
                uint32_t vfh[4];
                LDSM_X4_T(vfh, sVh + vb + np * 32);
                MMAH(o[2 * np],     p, vfh[0], vfh[1]);
                MMAH(o[2 * np + 1], p, vfh[2], vfh[3]);
            }
        }
    }

    float i0 = 1.0f / l0, i1 = 1.0f / l1;
    size_t r0 = (size_t)(b * T_ + qb + w * 16 + (lane >> 2)) * QS_ + h * DH_ + 2 * (lane & 3);
    size_t r1 = r0 + (size_t)8 * QS_;
#pragma unroll
    for (int nt = 0; nt < 16; nt++) {
        int cc = nt * 8;
        *(__half2*)(g_yh + r0 + cc) = __floats2half2_rn(o[nt][0] * i0, o[nt][1] * i0);
        *(__half2*)(g_yh + r1 + cc) = __floats2half2_rn(o[nt][2] * i1, o[nt][3] * i1);
    }
}

// ----------------------------------------------------------------------------
extern "C" void kernel_launch(void* const* d_in, const int* in_sizes, int n_in,
                              void* d_out, int out_size)
{
    const float* x    = (const float*)d_in[0];
    const float* fcos = (const float*)d_in[1];
    const float* fsin = (const float*)d_in[2];
    const float* wqkv = (const float*)d_in[3];
    const float* wo   = (const float*)d_in[4];
    float* out = (float*)d_out;

    __half *xh, *wh, *oh, *yh;
    cudaGetSymbolAddress((void**)&xh,  g_xh);
    cudaGetSymbolAddress((void**)&wh,  g_wh);
    cudaGetSymbolAddress((void**)&oh,  g_oh);
    cudaGetSymbolAddress((void**)&yh,  g_yh);

    cudaFuncSetAttribute(gemm1h_kernel,
                         cudaFuncAttributeMaxDynamicSharedMemorySize, GSMEM_);
    cudaFuncSetAttribute(attn_mma_kernel,
                         cudaFuncAttributeMaxDynamicSharedMemorySize, ASMEM);

    {
        int n4 = (M_ * D_) / 4;
        tohalf_kernel<<<(n4 + 255) / 256, 256>>>(x, xh, n4);
        n4 = (QKVN_ * D_) / 4;
        tohalf_kernel<<<(n4 + 255) / 256, 256>>>(wqkv, wh, n4);
        n4 = (D_ * QS_) / 4;
        tohalf_kernel<<<(n4 + 255) / 256, 256>>>(wo, oh, n4);
    }

    // QKV GEMM with fused RoPE + split epilogue (mode 1)
    gemm1h_kernel<<<dim3(QKVN_ / 128, M_ / 128), 256, GSMEM_>>>(
        xh, wh, nullptr, M_, QKVN_, D_, 1, fcos, fsin);

    attn_mma_kernel<<<dim3(T_ / 64, H_, B_), 128, ASMEM>>>();

    // output GEMM (mode 0)
    gemm1h_kernel<<<dim3(D_ / 128, M_ / 128), 256, GSMEM_>>>(
        yh, oh, out, M_, D_, QS_, 0, nullptr, nullptr);
}

// round 15
// speedup vs baseline: 6.4454x; 1.1009x over previous
#include <cuda_runtime.h>
#include <cuda_fp16.h>
#include <cstdint>

#define B_    2
#define T_    2048
#define D_    4096
#define H_    32
#define KVH_  8
#define DH_   128
#define QS_   (H_*DH_)
#define KS_   (KVH_*DH_)
#define QKVN_ (QS_ + 2*KS_)
#define M_    (B_*T_)

// Scratch
__device__ __half g_xh[(size_t)M_ * D_];
__device__ __half g_wh[(size_t)QKVN_ * D_];
__device__ __half g_oh[(size_t)D_ * QS_];
__device__ __half g_yh[(size_t)M_ * QS_];
__device__ __half g_Qh[(size_t)M_ * QS_];
__device__ __half g_Ql[(size_t)M_ * QS_];
__device__ __half g_Kh[(size_t)M_ * KS_];
__device__ __half g_Vh[(size_t)M_ * KS_];

// ---------------------------------------------------------------------------
__device__ __forceinline__ uint32_t smem_u32(const void* p) {
    uint32_t a;
    asm("{ .reg .u64 t; cvta.to.shared.u64 t, %1; cvt.u32.u64 %0, t; }"
        : "=r"(a) : "l"(p));
    return a;
}
__device__ __forceinline__ void cpasync16(uint32_t s, const void* g) {
    asm volatile("cp.async.cg.shared.global [%0], [%1], 16;" :: "r"(s), "l"(g));
}
#define CP_COMMIT() asm volatile("cp.async.commit_group;" ::: "memory")
#define CP_WAIT(N)  asm volatile("cp.async.wait_group %0;" :: "n"(N) : "memory")

#define LDSM_X4(r, addr)                                                      \
    asm volatile("ldmatrix.sync.aligned.m8n8.x4.shared.b16 {%0,%1,%2,%3}, [%4];" \
        : "=r"((r)[0]), "=r"((r)[1]), "=r"((r)[2]), "=r"((r)[3]) : "r"(addr))
#define LDSM_X4_T(r, addr)                                                    \
    asm volatile("ldmatrix.sync.aligned.m8n8.x4.trans.shared.b16 {%0,%1,%2,%3}, [%4];" \
        : "=r"((r)[0]), "=r"((r)[1]), "=r"((r)[2]), "=r"((r)[3]) : "r"(addr))

#define MMAH(d, a, b0, b1)                                                    \
    asm volatile("mma.sync.aligned.m16n8k16.row.col.f32.f16.f16.f32 "         \
        "{%0,%1,%2,%3}, {%4,%5,%6,%7}, {%8,%9}, {%0,%1,%2,%3};"               \
        : "+f"((d)[0]), "+f"((d)[1]), "+f"((d)[2]), "+f"((d)[3])              \
        : "r"((a)[0]), "r"((a)[1]), "r"((a)[2]), "r"((a)[3]), "r"(b0), "r"(b1))

__device__ __forceinline__ uint32_t packh2(float a, float b) {
    __half2 h = __floats2half2_rn(a, b);
    return *reinterpret_cast<uint32_t*>(&h);
}

// ---------------------------------------------------------------------------
// FP16 mma.sync GEMM: C = A*B^T. CTA 128x128, BK=64, 256 thr, 2 CTA/SM,
// 3-stage cp.async ring (prefetch distance 2, one sync / chunk), SW128
// swizzle (128B rows, chunk' = chunk ^ (row&7)).
// mode 0: fp32 C. mode 1 (QKV): fused RoPE + fp16 split to head-major planes.
// ---------------------------------------------------------------------------
#define PLN_   (128 * 128)         // 16384 B per plane
#define STGN   (2 * PLN_)          // 32768 B per stage (Ah,Bh)
#define GSMEM_ (3 * STGN)          // 98304 B

__global__ __launch_bounds__(256, 2) void gemm1h_kernel(
    const __half* __restrict__ Ah, const __half* __restrict__ Bh,
    float* __restrict__ C, int M, int N, int K, int mode,
    const float* __restrict__ pcos, const float* __restrict__ psin)
{
    extern __shared__ char smem[];
    const uint32_t sbase = smem_u32(smem);
    const int tid  = threadIdx.x;
    const int lane = tid & 31;
    const int wid  = tid >> 5;
    const int wm   = wid >> 1;
    const int wn   = wid & 1;

    const int bm = blockIdx.y * 128;
    const int bn = blockIdx.x * 128;
    const int nk = K >> 6;

    const __half* gp[2] = { Ah + (size_t)bm * K, Bh + (size_t)bn * K };

    const int lrow[4] = { tid >> 3, (tid + 256) >> 3, (tid + 512) >> 3, (tid + 768) >> 3 };
    const int lseg = tid & 7;

    float acc[2][8][4];
#pragma unroll
    for (int mt = 0; mt < 2; mt++)
#pragma unroll
        for (int nt = 0; nt < 8; nt++)
#pragma unroll
            for (int q = 0; q < 4; q++) acc[mt][nt][q] = 0.0f;

    const int rowA = lane & 15;
    const int hiA  = lane >> 4;
    const int rowB = (lane & 7) + ((lane & 16) ? 8 : 0);
    const int hiB  = (lane >> 3) & 1;
    uint32_t baseA[2]; int swzA[2];
#pragma unroll
    for (int mt = 0; mt < 2; mt++) {
        int r = wm * 32 + mt * 16 + rowA;
        baseA[mt] = (uint32_t)(r * 128);
        swzA[mt]  = r & 7;
    }
    uint32_t baseB[4]; int swzB[4];
#pragma unroll
    for (int np = 0; np < 4; np++) {
        int r = wn * 64 + np * 16 + rowB;
        baseB[np] = (uint32_t)(r * 128);
        swzB[np]  = r & 7;
    }

    // prologue: prefetch chunks 0,1 into stages 0,1
#pragma unroll
    for (int pc = 0; pc < 2; pc++) {
        const uint32_t st = sbase + pc * STGN;
        const int k0 = pc << 6;
#pragma unroll
        for (int p = 0; p < 2; p++) {
            uint32_t sb = st + p * PLN_;
#pragma unroll
            for (int j = 0; j < 4; j++) {
                int row = lrow[j];
                uint32_t so = (uint32_t)(row * 128 + ((lseg ^ (row & 7)) << 4));
                cpasync16(sb + so, gp[p] + (size_t)row * K + k0 + lseg * 8);
            }
        }
        CP_COMMIT();
    }

    int s_cur = 0;
    for (int c = 0; c < nk; c++) {
        if (c + 1 < nk) { CP_WAIT(1); } else { CP_WAIT(0); }
        __syncthreads();

        if (c + 2 < nk) {
            int s_pre = s_cur + 2; if (s_pre >= 3) s_pre -= 3;
            const uint32_t st = sbase + s_pre * STGN;
            const int k0 = (c + 2) << 6;
#pragma unroll
            for (int p = 0; p < 2; p++) {
                uint32_t sb = st + p * PLN_;
#pragma unroll
                for (int j = 0; j < 4; j++) {
                    int row = lrow[j];
                    uint32_t so = (uint32_t)(row * 128 + ((lseg ^ (row & 7)) << 4));
                    cpasync16(sb + so, gp[p] + (size_t)row * K + k0 + lseg * 8);
                }
            }
            CP_COMMIT();
        }

        const uint32_t st   = sbase + s_cur * STGN;
        const uint32_t sA_h = st;
        const uint32_t sB_h = st + PLN_;

#pragma unroll
        for (int ks = 0; ks < 4; ks++) {
            uint32_t ah[2][4];
#pragma unroll
            for (int mt = 0; mt < 2; mt++) {
                uint32_t off = baseA[mt] +
                    (uint32_t)((((ks * 2 + hiA) ^ swzA[mt]) & 7) << 4);
                LDSM_X4(ah[mt], sA_h + off);
            }
#pragma unroll
            for (int np = 0; np < 4; np++) {
                uint32_t bh[4];
                uint32_t off = baseB[np] +
                    (uint32_t)((((ks * 2 + hiB) ^ swzB[np]) & 7) << 4);
                LDSM_X4(bh, sB_h + off);
#pragma unroll
                for (int mt = 0; mt < 2; mt++)
#pragma unroll
                    for (int hf = 0; hf < 2; hf++)
                        MMAH(acc[mt][2 * np + hf], ah[mt], bh[2 * hf], bh[2 * hf + 1]);
            }
        }
        if (++s_cur == 3) s_cur = 0;
    }

    if (mode == 0) {
#pragma unroll
        for (int mt = 0; mt < 2; mt++) {
            const int r0 = bm + wm * 32 + mt * 16 + (lane >> 2);
#pragma unroll
            for (int nt = 0; nt < 8; nt++) {
                const int col = bn + wn * 64 + nt * 8 + (lane & 3) * 2;
                *(float2*)&C[(size_t)r0 * N + col] =
                    make_float2(acc[mt][nt][0], acc[mt][nt][1]);
                *(float2*)&C[(size_t)(r0 + 8) * N + col] =
                    make_float2(acc[mt][nt][2], acc[mt][nt][3]);
            }
        }
    } else {
        // fused RoPE + split: this CTA's 128 cols == head h
        const int h = bn >> 7;
#pragma unroll
        for (int mt = 0; mt < 2; mt++) {
            const int r0 = bm + wm * 32 + mt * 16 + (lane >> 2);
#pragma unroll
            for (int nt = 0; nt < 8; nt++) {
                const int cc = wn * 64 + nt * 8 + 2 * (lane & 3);
                const int i  = cc >> 1;
#pragma unroll
                for (int rr = 0; rr < 2; rr++) {
                    const int r = r0 + rr * 8;
                    const int t = r & (T_ - 1);
                    const int b = r >> 11;
                    float v0 = acc[mt][nt][rr * 2];
                    float v1 = acc[mt][nt][rr * 2 + 1];
                    if (h < 40) {
                        float cv = pcos[t * 64 + i];
                        float sv = psin[t * 64 + i];
                        float o0 = v0 * cv - v1 * sv;
                        float o1 = v0 * sv + v1 * cv;
                        v0 = o0; v1 = o1;
                    }
                    __half h0 = __float2half_rn(v0);
                    __half h1 = __float2half_rn(v1);
                    if (h < 32) {
                        size_t off = (((size_t)b * H_ + h) * T_ + t) * DH_ + cc;
                        *(__half2*)(g_Qh + off) = __halves2half2(h0, h1);
                        *(__half2*)(g_Ql + off) = __floats2half2_rn(
                            v0 - __half2float(h0), v1 - __half2float(h1));
                    } else if (h < 40) {
                        size_t off = (((size_t)b * KVH_ + (h - 32)) * T_ + t) * DH_ + cc;
                        *(__half2*)(g_Kh + off) = __halves2half2(h0, h1);
                    } else {
                        size_t off = (((size_t)b * KVH_ + (h - 40)) * T_ + t) * DH_ + cc;
                        *(__half2*)(g_Vh + off) = __halves2half2(h0, h1);
                    }
                }
            }
        }
    }
}

// fp32 -> fp16
__global__ void tohalf_kernel(const float* __restrict__ in,
                              __half* __restrict__ hi, int n4)
{
    int idx = blockIdx.x * blockDim.x + threadIdx.x;
    if (idx >= n4) return;
    float4 v = ((const float4*)in)[idx];
    __half2* hp = (__half2*)(hi + (size_t)idx * 4);
    hp[0] = __floats2half2_rn(v.x, v.y);
    hp[1] = __floats2half2_rn(v.z, v.w);
}

// ---------------------------------------------------------------------------
// mma.sync flash attention (causal, GQA), writes yh plane.
// S = (Qh+Ql)*Kh (2 terms); PV = P*Vh. Tile planes: Kh, Vh.
// 2-stage cp.async ring, one sync per key tile.
// ---------------------------------------------------------------------------
#define AST_B 272
#define APL_  (64 * AST_B)      // 17408
#define ASTG  (2 * APL_)        // 34816 (Kh, Vh)
#define ASMEM (2 * ASTG)        // 69632

__global__ __launch_bounds__(128, 2) void attn_mma_kernel()
{
    extern __shared__ char sm[];
    const uint32_t sbase = smem_u32(sm);

    const int tid = threadIdx.x, lane = tid & 31, w = tid >> 5;
    const int qb = (int)(gridDim.x - 1 - blockIdx.x) * 64;
    const int h  = blockIdx.y;
    const int b  = blockIdx.z;
    const int kh = h >> 2;

    const __half* gQh = g_Qh + ((size_t)b * H_ + h) * T_ * DH_;
    const __half* gQl = g_Ql + ((size_t)b * H_ + h) * T_ * DH_;
    const __half* gKh = g_Kh + ((size_t)b * KVH_ + kh) * T_ * DH_;
    const __half* gVh = g_Vh + ((size_t)b * KVH_ + kh) * T_ * DH_;

    // stage Q (2 planes fit exactly in stage 0)
#pragma unroll
    for (int k = 0; k < 8; k++) {
        int id = tid + 128 * k, r = id >> 4, sg = id & 15;
        cpasync16(sbase + r * AST_B + sg * 16,
                  (const char*)(gQh + (size_t)(qb + r) * DH_) + sg * 16);
        cpasync16(sbase + APL_ + r * AST_B + sg * 16,
                  (const char*)(gQl + (size_t)(qb + r) * DH_) + sg * 16);
    }
    CP_COMMIT(); CP_WAIT(0);
    __syncthreads();

    uint32_t qh_[8][4], ql_[8][4];
    {
        uint32_t base = (uint32_t)((w * 16 + (lane & 15)) * AST_B + (lane >> 4) * 16);
#pragma unroll
        for (int ks = 0; ks < 8; ks++) {
            LDSM_X4(qh_[ks], sbase + base + ks * 32);
            LDSM_X4(ql_[ks], sbase + APL_ + base + ks * 32);
        }
    }
    __syncthreads();

    const int last = qb >> 6;

    // prologue: prefetch tile 0 into stage 0
#pragma unroll
    for (int k = 0; k < 8; k++) {
        int id = tid + 128 * k, r = id >> 4, sg = id & 15;
        size_t grow = (size_t)r * DH_;
        uint32_t soff = (uint32_t)(r * AST_B + sg * 16);
        cpasync16(sbase + soff,        (const char*)(gKh + grow) + sg * 16);
        cpasync16(sbase + APL_ + soff, (const char*)(gVh + grow) + sg * 16);
    }
    CP_COMMIT();

    float o[16][4];
#pragma unroll
    for (int nt = 0; nt < 16; nt++)
#pragma unroll
        for (int q = 0; q < 4; q++) o[nt][q] = 0.0f;
    float m0 = -1e30f, m1 = -1e30f, l0 = 0.0f, l1 = 0.0f;

    const int rowB = (lane & 7) + ((lane & 16) ? 8 : 0);
    const int colB = ((lane >> 3) & 1) * 16;
    const int qrow0 = qb + w * 16 + (lane >> 2);
    const int qrow1 = qrow0 + 8;
    const float sc = 0.08838834764831845f;

    for (int kb = 0; kb <= last; kb++) {
        CP_WAIT(0);
        __syncthreads();

        const uint32_t stc = sbase + (uint32_t)(kb & 1) * ASTG;
        if (kb < last) {
            const uint32_t stn = sbase + (uint32_t)((kb + 1) & 1) * ASTG;
#pragma unroll
            for (int k = 0; k < 8; k++) {
                int id = tid + 128 * k, r = id >> 4, sg = id & 15;
                size_t grow = (size_t)((kb + 1) * 64 + r) * DH_;
                uint32_t soff = (uint32_t)(r * AST_B + sg * 16);
                cpasync16(stn + soff,        (const char*)(gKh + grow) + sg * 16);
                cpasync16(stn + APL_ + soff, (const char*)(gVh + grow) + sg * 16);
            }
            CP_COMMIT();
        }

        const uint32_t sKh = stc;
        const uint32_t sVh = stc + APL_;

        float s[8][4];
#pragma unroll
        for (int nt = 0; nt < 8; nt++)
#pragma unroll
            for (int q = 0; q < 4; q++) s[nt][q] = 0.0f;

#pragma unroll
        for (int ks = 0; ks < 8; ks++) {
            uint32_t kfh[4][4];
#pragma unroll
            for (int pr = 0; pr < 4; pr++) {
                uint32_t off = (uint32_t)((pr * 16 + rowB) * AST_B + colB + ks * 32);
                LDSM_X4(kfh[pr], sKh + off);
            }
#pragma unroll
            for (int pr = 0; pr < 4; pr++)
#pragma unroll
                for (int hf = 0; hf < 2; hf++) {
                    int nt = 2 * pr + hf;
                    MMAH(s[nt], qh_[ks], kfh[pr][2 * hf], kfh[pr][2 * hf + 1]);
                    MMAH(s[nt], ql_[ks], kfh[pr][2 * hf], kfh[pr][2 * hf + 1]);
                }
        }

        float mx0 = -1e30f, mx1 = -1e30f;
        const bool dg = (kb == last);
#pragma unroll
        for (int nt = 0; nt < 8; nt++) {
            int c0 = kb * 64 + nt * 8 + 2 * (lane & 3);
#pragma unroll
            for (int q = 0; q < 4; q++) s[nt][q] *= sc;
            if (dg) {
                if (c0     > qrow0) s[nt][0] = -1e30f;
                if (c0 + 1 > qrow0) s[nt][1] = -1e30f;
                if (c0     > qrow1) s[nt][2] = -1e30f;
                if (c0 + 1 > qrow1) s[nt][3] = -1e30f;
            }
            mx0 = fmaxf(mx0, fmaxf(s[nt][0], s[nt][1]));
            mx1 = fmaxf(mx1, fmaxf(s[nt][2], s[nt][3]));
        }
        mx0 = fmaxf(mx0, __shfl_xor_sync(0xffffffffu, mx0, 1));
        mx0 = fmaxf(mx0, __shfl_xor_sync(0xffffffffu, mx0, 2));
        mx1 = fmaxf(mx1, __shfl_xor_sync(0xffffffffu, mx1, 1));
        mx1 = fmaxf(mx1, __shfl_xor_sync(0xffffffffu, mx1, 2));

        float mn0 = fmaxf(m0, mx0), mn1 = fmaxf(m1, mx1);
        float cr0 = __expf(m0 - mn0), cr1 = __expf(m1 - mn1);
        float sum0 = 0.0f, sum1 = 0.0f;
#pragma unroll
        for (int nt = 0; nt < 8; nt++) {
            s[nt][0] = __expf(s[nt][0] - mn0);
            s[nt][1] = __expf(s[nt][1] - mn0);
            s[nt][2] = __expf(s[nt][2] - mn1);
            s[nt][3] = __expf(s[nt][3] - mn1);
            sum0 += s[nt][0] + s[nt][1];
            sum1 += s[nt][2] + s[nt][3];
        }
        sum0 += __shfl_xor_sync(0xffffffffu, sum0, 1);
        sum0 += __shfl_xor_sync(0xffffffffu, sum0, 2);
        sum1 += __shfl_xor_sync(0xffffffffu, sum1, 1);
        sum1 += __shfl_xor_sync(0xffffffffu, sum1, 2);
        l0 = l0 * cr0 + sum0;  m0 = mn0;
        l1 = l1 * cr1 + sum1;  m1 = mn1;
#pragma unroll
        for (int nt = 0; nt < 16; nt++) {
            o[nt][0] *= cr0; o[nt][1] *= cr0;
            o[nt][2] *= cr1; o[nt][3] *= cr1;
        }

#pragma unroll
        for (int ks = 0; ks < 4; ks++) {
            uint32_t p[4];
            p[0] = packh2(s[2 * ks][0],     s[2 * ks][1]);
            p[1] = packh2(s[2 * ks][2],     s[2 * ks][3]);
            p[2] = packh2(s[2 * ks + 1][0], s[2 * ks + 1][1]);
            p[3] = packh2(s[2 * ks + 1][2], s[2 * ks + 1][3]);
            uint32_t vb = (uint32_t)((ks * 16 + (lane & 15)) * AST_B + (lane >> 4) * 16);
#pragma unroll
            for (int np = 0; np < 8; np++) {
                uint32_t vfh[4];
                LDSM_X4_T(vfh, sVh + vb + np * 32);
                MMAH(o[2 * np],     p, vfh[0], vfh[1]);
                MMAH(o[2 * np + 1], p, vfh[2], vfh[3]);
            }
        }
    }

    float i0 = 1.0f / l0, i1 = 1.0f / l1;
    size_t r0 = (size_t)(b * T_ + qb + w * 16 + (lane >> 2)) * QS_ + h * DH_ + 2 * (lane & 3);
    size_t r1 = r0 + (size_t)8 * QS_;
#pragma unroll
    for (int nt = 0; nt < 16; nt++) {
        int cc = nt * 8;
        *(__half2*)(g_yh + r0 + cc) = __floats2half2_rn(o[nt][0] * i0, o[nt][1] * i0);
        *(__half2*)(g_yh + r1 + cc) = __floats2half2_rn(o[nt][2] * i1, o[nt][3] * i1);
    }
}

// ----------------------------------------------------------------------------
extern "C" void kernel_launch(void* const* d_in, const int* in_sizes, int n_in,
                              void* d_out, int out_size)
{
    const float* x    = (const float*)d_in[0];
    const float* fcos = (const float*)d_in[1];
    const float* fsin = (const float*)d_in[2];
    const float* wqkv = (const float*)d_in[3];
    const float* wo   = (const float*)d_in[4];
    float* out = (float*)d_out;

    __half *xh, *wh, *oh, *yh;
    cudaGetSymbolAddress((void**)&xh,  g_xh);
    cudaGetSymbolAddress((void**)&wh,  g_wh);
    cudaGetSymbolAddress((void**)&oh,  g_oh);
    cudaGetSymbolAddress((void**)&yh,  g_yh);

    cudaFuncSetAttribute(gemm1h_kernel,
                         cudaFuncAttributeMaxDynamicSharedMemorySize, GSMEM_);
    cudaFuncSetAttribute(attn_mma_kernel,
                         cudaFuncAttributeMaxDynamicSharedMemorySize, ASMEM);

    {
        int n4 = (M_ * D_) / 4;
        tohalf_kernel<<<(n4 + 255) / 256, 256>>>(x, xh, n4);
        n4 = (QKVN_ * D_) / 4;
        tohalf_kernel<<<(n4 + 255) / 256, 256>>>(wqkv, wh, n4);
        n4 = (D_ * QS_) / 4;
        tohalf_kernel<<<(n4 + 255) / 256, 256>>>(wo, oh, n4);
    }

    // QKV GEMM with fused RoPE + split epilogue (mode 1)
    gemm1h_kernel<<<dim3(QKVN_ / 128, M_ / 128), 256, GSMEM_>>>(
        xh, wh, nullptr, M_, QKVN_, D_, 1, fcos, fsin);

    attn_mma_kernel<<<dim3(T_ / 64, H_, B_), 128, ASMEM>>>();

    // output GEMM (mode 0)
    gemm1h_kernel<<<dim3(D_ / 128, M_ / 128), 256, GSMEM_>>>(
        yh, oh, out, M_, D_, QS_, 0, nullptr, nullptr);
}

// round 16
// speedup vs baseline: 6.4881x; 1.0066x over previous
#include <cuda_runtime.h>
#include <cuda_fp16.h>
#include <cstdint>

#define B_    2
#define T_    2048
#define D_    4096
#define H_    32
#define KVH_  8
#define DH_   128
#define QS_   (H_*DH_)
#define KS_   (KVH_*DH_)
#define QKVN_ (QS_ + 2*KS_)
#define M_    (B_*T_)

// Scratch
__device__ __half g_xh[(size_t)M_ * D_];
__device__ __half g_wh[(size_t)QKVN_ * D_];
__device__ __half g_oh[(size_t)D_ * QS_];
__device__ __half g_yh[(size_t)M_ * QS_];
__device__ __half g_Qh[(size_t)M_ * QS_];
__device__ __half g_Kh[(size_t)M_ * KS_];
__device__ __half g_Vh[(size_t)M_ * KS_];

// ---------------------------------------------------------------------------
__device__ __forceinline__ uint32_t smem_u32(const void* p) {
    uint32_t a;
    asm("{ .reg .u64 t; cvta.to.shared.u64 t, %1; cvt.u32.u64 %0, t; }"
        : "=r"(a) : "l"(p));
    return a;
}
__device__ __forceinline__ void cpasync16(uint32_t s, const void* g) {
    asm volatile("cp.async.cg.shared.global [%0], [%1], 16;" :: "r"(s), "l"(g));
}
#define CP_COMMIT() asm volatile("cp.async.commit_group;" ::: "memory")
#define CP_WAIT(N)  asm volatile("cp.async.wait_group %0;" :: "n"(N) : "memory")

#define LDSM_X4(r, addr)                                                      \
    asm volatile("ldmatrix.sync.aligned.m8n8.x4.shared.b16 {%0,%1,%2,%3}, [%4];" \
        : "=r"((r)[0]), "=r"((r)[1]), "=r"((r)[2]), "=r"((r)[3]) : "r"(addr))
#define LDSM_X4_T(r, addr)                                                    \
    asm volatile("ldmatrix.sync.aligned.m8n8.x4.trans.shared.b16 {%0,%1,%2,%3}, [%4];" \
        : "=r"((r)[0]), "=r"((r)[1]), "=r"((r)[2]), "=r"((r)[3]) : "r"(addr))

#define MMAH(d, a, b0, b1)                                                    \
    asm volatile("mma.sync.aligned.m16n8k16.row.col.f32.f16.f16.f32 "         \
        "{%0,%1,%2,%3}, {%4,%5,%6,%7}, {%8,%9}, {%0,%1,%2,%3};"               \
        : "+f"((d)[0]), "+f"((d)[1]), "+f"((d)[2]), "+f"((d)[3])              \
        : "r"((a)[0]), "r"((a)[1]), "r"((a)[2]), "r"((a)[3]), "r"(b0), "r"(b1))

__device__ __forceinline__ uint32_t packh2(float a, float b) {
    __half2 h = __floats2half2_rn(a, b);
    return *reinterpret_cast<uint32_t*>(&h);
}

// ---------------------------------------------------------------------------
// FP16 mma.sync GEMM: C = A*B^T. CTA 128x128, BK=64, 256 thr, 2 CTA/SM,
// 3-stage cp.async ring (prefetch distance 2, one sync / chunk), SW128
// swizzle (128B rows, chunk' = chunk ^ (row&7)).
// mode 0: fp32 C. mode 1 (QKV): fused RoPE + fp16 store to head-major planes.
// ---------------------------------------------------------------------------
#define PLN_   (128 * 128)         // 16384 B per plane
#define STGN   (2 * PLN_)          // 32768 B per stage (Ah,Bh)
#define GSMEM_ (3 * STGN)          // 98304 B

__global__ __launch_bounds__(256, 2) void gemm1h_kernel(
    const __half* __restrict__ Ah, const __half* __restrict__ Bh,
    float* __restrict__ C, int M, int N, int K, int mode,
    const float* __restrict__ pcos, const float* __restrict__ psin)
{
    extern __shared__ char smem[];
    const uint32_t sbase = smem_u32(smem);
    const int tid  = threadIdx.x;
    const int lane = tid & 31;
    const int wid  = tid >> 5;
    const int wm   = wid >> 1;
    const int wn   = wid & 1;

    const int bm = blockIdx.y * 128;
    const int bn = blockIdx.x * 128;
    const int nk = K >> 6;

    const __half* gp[2] = { Ah + (size_t)bm * K, Bh + (size_t)bn * K };

    const int lrow[4] = { tid >> 3, (tid + 256) >> 3, (tid + 512) >> 3, (tid + 768) >> 3 };
    const int lseg = tid & 7;

    float acc[2][8][4];
#pragma unroll
    for (int mt = 0; mt < 2; mt++)
#pragma unroll
        for (int nt = 0; nt < 8; nt++)
#pragma unroll
            for (int q = 0; q < 4; q++) acc[mt][nt][q] = 0.0f;

    const int rowA = lane & 15;
    const int hiA  = lane >> 4;
    const int rowB = (lane & 7) + ((lane & 16) ? 8 : 0);
    const int hiB  = (lane >> 3) & 1;
    uint32_t baseA[2]; int swzA[2];
#pragma unroll
    for (int mt = 0; mt < 2; mt++) {
        int r = wm * 32 + mt * 16 + rowA;
        baseA[mt] = (uint32_t)(r * 128);
        swzA[mt]  = r & 7;
    }
    uint32_t baseB[4]; int swzB[4];
#pragma unroll
    for (int np = 0; np < 4; np++) {
        int r = wn * 64 + np * 16 + rowB;
        baseB[np] = (uint32_t)(r * 128);
        swzB[np]  = r & 7;
    }

    // prologue: prefetch chunks 0,1 into stages 0,1
#pragma unroll
    for (int pc = 0; pc < 2; pc++) {
        const uint32_t st = sbase + pc * STGN;
        const int k0 = pc << 6;
#pragma unroll
        for (int p = 0; p < 2; p++) {
            uint32_t sb = st + p * PLN_;
#pragma unroll
            for (int j = 0; j < 4; j++) {
                int row = lrow[j];
                uint32_t so = (uint32_t)(row * 128 + ((lseg ^ (row & 7)) << 4));
                cpasync16(sb + so, gp[p] + (size_t)row * K + k0 + lseg * 8);
            }
        }
        CP_COMMIT();
    }

    int s_cur = 0;
    for (int c = 0; c < nk; c++) {
        if (c + 1 < nk) { CP_WAIT(1); } else { CP_WAIT(0); }
        __syncthreads();

        if (c + 2 < nk) {
            int s_pre = s_cur + 2; if (s_pre >= 3) s_pre -= 3;
            const uint32_t st = sbase + s_pre * STGN;
            const int k0 = (c + 2) << 6;
#pragma unroll
            for (int p = 0; p < 2; p++) {
                uint32_t sb = st + p * PLN_;
#pragma unroll
                for (int j = 0; j < 4; j++) {
                    int row = lrow[j];
                    uint32_t so = (uint32_t)(row * 128 + ((lseg ^ (row & 7)) << 4));
                    cpasync16(sb + so, gp[p] + (size_t)row * K + k0 + lseg * 8);
                }
            }
            CP_COMMIT();
        }

        const uint32_t st   = sbase + s_cur * STGN;
        const uint32_t sA_h = st;
        const uint32_t sB_h = st + PLN_;

#pragma unroll
        for (int ks = 0; ks < 4; ks++) {
            uint32_t ah[2][4];
#pragma unroll
            for (int mt = 0; mt < 2; mt++) {
                uint32_t off = baseA[mt] +
                    (uint32_t)((((ks * 2 + hiA) ^ swzA[mt]) & 7) << 4);
                LDSM_X4(ah[mt], sA_h + off);
            }
#pragma unroll
            for (int np = 0; np < 4; np++) {
                uint32_t bh[4];
                uint32_t off = baseB[np] +
                    (uint32_t)((((ks * 2 + hiB) ^ swzB[np]) & 7) << 4);
                LDSM_X4(bh, sB_h + off);
#pragma unroll
                for (int mt = 0; mt < 2; mt++)
#pragma unroll
                    for (int hf = 0; hf < 2; hf++)
                        MMAH(acc[mt][2 * np + hf], ah[mt], bh[2 * hf], bh[2 * hf + 1]);
            }
        }
        if (++s_cur == 3) s_cur = 0;
    }

    if (mode == 0) {
#pragma unroll
        for (int mt = 0; mt < 2; mt++) {
            const int r0 = bm + wm * 32 + mt * 16 + (lane >> 2);
#pragma unroll
            for (int nt = 0; nt < 8; nt++) {
                const int col = bn + wn * 64 + nt * 8 + (lane & 3) * 2;
                *(float2*)&C[(size_t)r0 * N + col] =
                    make_float2(acc[mt][nt][0], acc[mt][nt][1]);
                *(float2*)&C[(size_t)(r0 + 8) * N + col] =
                    make_float2(acc[mt][nt][2], acc[mt][nt][3]);
            }
        }
    } else {
        // fused RoPE + store: this CTA's 128 cols == head h
        const int h = bn >> 7;
#pragma unroll
        for (int mt = 0; mt < 2; mt++) {
            const int r0 = bm + wm * 32 + mt * 16 + (lane >> 2);
#pragma unroll
            for (int nt = 0; nt < 8; nt++) {
                const int cc = wn * 64 + nt * 8 + 2 * (lane & 3);
                const int i  = cc >> 1;
#pragma unroll
                for (int rr = 0; rr < 2; rr++) {
                    const int r = r0 + rr * 8;
                    const int t = r & (T_ - 1);
                    const int b = r >> 11;
                    float v0 = acc[mt][nt][rr * 2];
                    float v1 = acc[mt][nt][rr * 2 + 1];
                    if (h < 40) {
                        float cv = pcos[t * 64 + i];
                        float sv = psin[t * 64 + i];
                        float o0 = v0 * cv - v1 * sv;
                        float o1 = v0 * sv + v1 * cv;
                        v0 = o0; v1 = o1;
                    }
                    __half2 hv = __floats2half2_rn(v0, v1);
                    if (h < 32) {
                        size_t off = (((size_t)b * H_ + h) * T_ + t) * DH_ + cc;
                        *(__half2*)(g_Qh + off) = hv;
                    } else if (h < 40) {
                        size_t off = (((size_t)b * KVH_ + (h - 32)) * T_ + t) * DH_ + cc;
                        *(__half2*)(g_Kh + off) = hv;
                    } else {
                        size_t off = (((size_t)b * KVH_ + (h - 40)) * T_ + t) * DH_ + cc;
                        *(__half2*)(g_Vh + off) = hv;
                    }
                }
            }
        }
    }
}

// fp32 -> fp16, 4 float4 per thread for MLP
__global__ void tohalf_kernel(const float* __restrict__ in,
                              __half* __restrict__ hi, int n4)
{
    int base = (blockIdx.x * blockDim.x + threadIdx.x) * 4;
#pragma unroll
    for (int j = 0; j < 4; j++) {
        int idx = base + j;
        if (idx >= n4) return;
        float4 v = ((const float4*)in)[idx];
        __half2* hp = (__half2*)(hi + (size_t)idx * 4);
        hp[0] = __floats2half2_rn(v.x, v.y);
        hp[1] = __floats2half2_rn(v.z, v.w);
    }
}

// ---------------------------------------------------------------------------
// fp16 mma.sync flash attention (causal, GQA), writes yh plane.
// S = Qh*Kh; PV = P*Vh. Tile planes: Kh, Vh. 2-stage ring, one sync/tile.
// ---------------------------------------------------------------------------
#define AST_B 272
#define APL_  (64 * AST_B)      // 17408
#define ASTG  (2 * APL_)        // 34816 (Kh, Vh)
#define ASMEM (2 * ASTG)        // 69632

__global__ __launch_bounds__(128, 2) void attn_mma_kernel()
{
    extern __shared__ char sm[];
    const uint32_t sbase = smem_u32(sm);

    const int tid = threadIdx.x, lane = tid & 31, w = tid >> 5;
    const int qb = (int)(gridDim.x - 1 - blockIdx.x) * 64;
    const int h  = blockIdx.y;
    const int b  = blockIdx.z;
    const int kh = h >> 2;

    const __half* gQh = g_Qh + ((size_t)b * H_ + h) * T_ * DH_;
    const __half* gKh = g_Kh + ((size_t)b * KVH_ + kh) * T_ * DH_;
    const __half* gVh = g_Vh + ((size_t)b * KVH_ + kh) * T_ * DH_;

    // stage Q into stage0 plane 0
#pragma unroll
    for (int k = 0; k < 8; k++) {
        int id = tid + 128 * k, r = id >> 4, sg = id & 15;
        cpasync16(sbase + r * AST_B + sg * 16,
                  (const char*)(gQh + (size_t)(qb + r) * DH_) + sg * 16);
    }
    CP_COMMIT(); CP_WAIT(0);
    __syncthreads();

    uint32_t qh_[8][4];
    {
        uint32_t base = (uint32_t)((w * 16 + (lane & 15)) * AST_B + (lane >> 4) * 16);
#pragma unroll
        for (int ks = 0; ks < 8; ks++)
            LDSM_X4(qh_[ks], sbase + base + ks * 32);
    }
    __syncthreads();

    const int last = qb >> 6;

    // prologue: prefetch tile 0 into stage 0
#pragma unroll
    for (int k = 0; k < 8; k++) {
        int id = tid + 128 * k, r = id >> 4, sg = id & 15;
        size_t grow = (size_t)r * DH_;
        uint32_t soff = (uint32_t)(r * AST_B + sg * 16);
        cpasync16(sbase + soff,        (const char*)(gKh + grow) + sg * 16);
        cpasync16(sbase + APL_ + soff, (const char*)(gVh + grow) + sg * 16);
    }
    CP_COMMIT();

    float o[16][4];
#pragma unroll
    for (int nt = 0; nt < 16; nt++)
#pragma unroll
        for (int q = 0; q < 4; q++) o[nt][q] = 0.0f;
    float m0 = -1e30f, m1 = -1e30f, l0 = 0.0f, l1 = 0.0f;

    const int rowB = (lane & 7) + ((lane & 16) ? 8 : 0);
    const int colB = ((lane >> 3) & 1) * 16;
    const int qrow0 = qb + w * 16 + (lane >> 2);
    const int qrow1 = qrow0 + 8;
    const float sc = 0.08838834764831845f;

    for (int kb = 0; kb <= last; kb++) {
        CP_WAIT(0);
        __syncthreads();

        const uint32_t stc = sbase + (uint32_t)(kb & 1) * ASTG;
        if (kb < last) {
            const uint32_t stn = sbase + (uint32_t)((kb + 1) & 1) * ASTG;
#pragma unroll
            for (int k = 0; k < 8; k++) {
                int id = tid + 128 * k, r = id >> 4, sg = id & 15;
                size_t grow = (size_t)((kb + 1) * 64 + r) * DH_;
                uint32_t soff = (uint32_t)(r * AST_B + sg * 16);
                cpasync16(stn + soff,        (const char*)(gKh + grow) + sg * 16);
                cpasync16(stn + APL_ + soff, (const char*)(gVh + grow) + sg * 16);
            }
            CP_COMMIT();
        }

        const uint32_t sKh = stc;
        const uint32_t sVh = stc + APL_;

        float s[8][4];
#pragma unroll
        for (int nt = 0; nt < 8; nt++)
#pragma unroll
            for (int q = 0; q < 4; q++) s[nt][q] = 0.0f;

#pragma unroll
        for (int ks = 0; ks < 8; ks++) {
            uint32_t kfh[4][4];
#pragma unroll
            for (int pr = 0; pr < 4; pr++) {
                uint32_t off = (uint32_t)((pr * 16 + rowB) * AST_B + colB + ks * 32);
                LDSM_X4(kfh[pr], sKh + off);
            }
#pragma unroll
            for (int pr = 0; pr < 4; pr++)
#pragma unroll
                for (int hf = 0; hf < 2; hf++)
                    MMAH(s[2 * pr + hf], qh_[ks], kfh[pr][2 * hf], kfh[pr][2 * hf + 1]);
        }

        float mx0 = -1e30f, mx1 = -1e30f;
        const bool dg = (kb == last);
#pragma unroll
        for (int nt = 0; nt < 8; nt++) {
            int c0 = kb * 64 + nt * 8 + 2 * (lane & 3);
#pragma unroll
            for (int q = 0; q < 4; q++) s[nt][q] *= sc;
            if (dg) {
                if (c0     > qrow0) s[nt][0] = -1e30f;
                if (c0 + 1 > qrow0) s[nt][1] = -1e30f;
                if (c0     > qrow1) s[nt][2] = -1e30f;
                if (c0 + 1 > qrow1) s[nt][3] = -1e30f;
            }
            mx0 = fmaxf(mx0, fmaxf(s[nt][0], s[nt][1]));
            mx1 = fmaxf(mx1, fmaxf(s[nt][2], s[nt][3]));
        }
        mx0 = fmaxf(mx0, __shfl_xor_sync(0xffffffffu, mx0, 1));
        mx0 = fmaxf(mx0, __shfl_xor_sync(0xffffffffu, mx0, 2));
        mx1 = fmaxf(mx1, __shfl_xor_sync(0xffffffffu, mx1, 1));
        mx1 = fmaxf(mx1, __shfl_xor_sync(0xffffffffu, mx1, 2));

        float mn0 = fmaxf(m0, mx0), mn1 = fmaxf(m1, mx1);
        float cr0 = __expf(m0 - mn0), cr1 = __expf(m1 - mn1);
        float sum0 = 0.0f, sum1 = 0.0f;
#pragma unroll
        for (int nt = 0; nt < 8; nt++) {
            s[nt][0] = __expf(s[nt][0] - mn0);
            s[nt][1] = __expf(s[nt][1] - mn0);
            s[nt][2] = __expf(s[nt][2] - mn1);
            s[nt][3] = __expf(s[nt][3] - mn1);
            sum0 += s[nt][0] + s[nt][1];
            sum1 += s[nt][2] + s[nt][3];
        }
        sum0 += __shfl_xor_sync(0xffffffffu, sum0, 1);
        sum0 += __shfl_xor_sync(0xffffffffu, sum0, 2);
        sum1 += __shfl_xor_sync(0xffffffffu, sum1, 1);
        sum1 += __shfl_xor_sync(0xffffffffu, sum1, 2);
        l0 = l0 * cr0 + sum0;  m0 = mn0;
        l1 = l1 * cr1 + sum1;  m1 = mn1;
#pragma unroll
        for (int nt = 0; nt < 16; nt++) {
            o[nt][0] *= cr0; o[nt][1] *= cr0;
            o[nt][2] *= cr1; o[nt][3] *= cr1;
        }

#pragma unroll
        for (int ks = 0; ks < 4; ks++) {
            uint32_t p[4];
            p[0] = packh2(s[2 * ks][0],     s[2 * ks][1]);
            p[1] = packh2(s[2 * ks][2],     s[2 * ks][3]);
            p[2] = packh2(s[2 * ks + 1][0], s[2 * ks + 1][1]);
            p[3] = packh2(s[2 * ks + 1][2], s[2 * ks + 1][3]);
            uint32_t vb = (uint32_t)((ks * 16 + (lane & 15)) * AST_B + (lane >> 4) * 16);
#pragma unroll
            for (int np = 0; np < 8; np++) {
                uint32_t vfh[4];
                LDSM_X4_T(vfh, sVh + vb + np * 32);
                MMAH(o[2 * np],     p, vfh[0], vfh[1]);
                MMAH(o[2 * np + 1], p, vfh[2], vfh[3]);
            }
        }
    }

    float i0 = 1.0f / l0, i1 = 1.0f / l1;
    size_t r0 = (size_t)(b * T_ + qb + w * 16 + (lane >> 2)) * QS_ + h * DH_ + 2 * (lane & 3);
    size_t r1 = r0 + (size_t)8 * QS_;
#pragma unroll
    for (int nt = 0; nt < 16; nt++) {
        int cc = nt * 8;
        *(__half2*)(g_yh + r0 + cc) = __floats2half2_rn(o[nt][0] * i0, o[nt][1] * i0);
        *(__half2*)(g_yh + r1 + cc) = __floats2half2_rn(o[nt][2] * i1, o[nt][3] * i1);
    }
}

// ----------------------------------------------------------------------------
extern "C" void kernel_launch(void* const* d_in, const int* in_sizes, int n_in,
                              void* d_out, int out_size)
{
    const float* x    = (const float*)d_in[0];
    const float* fcos = (const float*)d_in[1];
    const float* fsin = (const float*)d_in[2];
    const float* wqkv = (const float*)d_in[3];
    const float* wo   = (const float*)d_in[4];
    float* out = (float*)d_out;

    __half *xh, *wh, *oh, *yh;
    cudaGetSymbolAddress((void**)&xh,  g_xh);
    cudaGetSymbolAddress((void**)&wh,  g_wh);
    cudaGetSymbolAddress((void**)&oh,  g_oh);
    cudaGetSymbolAddress((void**)&yh,  g_yh);

    cudaFuncSetAttribute(gemm1h_kernel,
                         cudaFuncAttributeMaxDynamicSharedMemorySize, GSMEM_);
    cudaFuncSetAttribute(attn_mma_kernel,
                         cudaFuncAttributeMaxDynamicSharedMemorySize, ASMEM);

    {
        int n4 = (M_ * D_) / 4;
        tohalf_kernel<<<(n4 / 4 + 255) / 256, 256>>>(x, xh, n4);
        n4 = (QKVN_ * D_) / 4;
        tohalf_kernel<<<(n4 / 4 + 255) / 256, 256>>>(wqkv, wh, n4);
        n4 = (D_ * QS_) / 4;
        tohalf_kernel<<<(n4 / 4 + 255) / 256, 256>>>(wo, oh, n4);
    }

    // QKV GEMM with fused RoPE epilogue (mode 1)
    gemm1h_kernel<<<dim3(QKVN_ / 128, M_ / 128), 256, GSMEM_>>>(
        xh, wh, nullptr, M_, QKVN_, D_, 1, fcos, fsin);

    attn_mma_kernel<<<dim3(T_ / 64, H_, B_), 128, ASMEM>>>();

    // output GEMM (mode 0)
    gemm1h_kernel<<<dim3(D_ / 128, M_ / 128), 256, GSMEM_>>>(
        yh, oh, out, M_, D_, QS_, 0, nullptr, nullptr);
}